// round 1
// baseline (speedup 1.0000x reference)
#include <cuda_runtime.h>

#define B_ 4
#define N_ 2048
#define C_ 1024
#define H_ 16
#define D_ 64
#define M_ (B_*N_)              // 8192 tokens
#define BHND (B_*H_*N_*D_)      // 8388608 elements per Q/K/V tensor

// Scratch (alloc-free rule: __device__ globals)
__device__ float g_qkv[(size_t)3*BHND];      // [s][b][h][n][d]
__device__ float g_attn[(size_t)M_*C_];      // [b*N+n][h*D+d]

// ----------------------------------------------------------------------------
// GEMM: C = A @ W^T (+bias). A [M,K] row-major, W [Nc,K] row-major.
// 128x128x16 block tile, 256 threads, 8x8 per-thread microtile.
// MODE 0: A = x (param), epilogue scatters into g_qkv [s][b][h][n][d]
// MODE 1: A = g_attn,    epilogue adds bias, writes Cout (d_out)
// ----------------------------------------------------------------------------
template<int MODE>
__global__ __launch_bounds__(256) void gemm_nt(const float* __restrict__ A,
                                               const float* __restrict__ W,
                                               const float* __restrict__ bias,
                                               float* __restrict__ Cout,
                                               int M, int Nc, int K)
{
    __shared__ float As[16][132];   // [k][m], padded vs bank conflicts
    __shared__ float Bs[16][132];   // [k][n]

    const int tid = threadIdx.x;
    const int tx = tid & 15;        // 0..15 -> col groups
    const int ty = tid >> 4;        // 0..15 -> row groups
    const int m0 = blockIdx.y * 128;
    const int n0 = blockIdx.x * 128;

    const float* Ap = (MODE == 1) ? g_attn : A;

    float acc[8][8];
    #pragma unroll
    for (int i = 0; i < 8; i++)
        #pragma unroll
        for (int j = 0; j < 8; j++) acc[i][j] = 0.f;

    for (int k0 = 0; k0 < K; k0 += 16) {
        // cooperative load: 512 float4 slots for A tile, 512 for B tile
        #pragma unroll
        for (int i = 0; i < 2; i++) {
            int lin = tid + i * 256;         // 0..511
            int row = lin >> 2;              // 0..127
            int c4  = lin & 3;               // 0..3 (k offset /4)
            float4 av = *(const float4*)&Ap[(size_t)(m0 + row) * K + k0 + c4 * 4];
            As[c4*4+0][row] = av.x; As[c4*4+1][row] = av.y;
            As[c4*4+2][row] = av.z; As[c4*4+3][row] = av.w;
            float4 bv = *(const float4*)&W[(size_t)(n0 + row) * K + k0 + c4 * 4];
            Bs[c4*4+0][row] = bv.x; Bs[c4*4+1][row] = bv.y;
            Bs[c4*4+2][row] = bv.z; Bs[c4*4+3][row] = bv.w;
        }
        __syncthreads();

        #pragma unroll
        for (int kk = 0; kk < 16; kk++) {
            float a[8], b[8];
            *(float4*)(a)     = *(float4*)&As[kk][ty*4];
            *(float4*)(a + 4) = *(float4*)&As[kk][64 + ty*4];
            *(float4*)(b)     = *(float4*)&Bs[kk][tx*4];
            *(float4*)(b + 4) = *(float4*)&Bs[kk][64 + tx*4];
            #pragma unroll
            for (int i = 0; i < 8; i++)
                #pragma unroll
                for (int j = 0; j < 8; j++)
                    acc[i][j] = fmaf(a[i], b[j], acc[i][j]);
        }
        __syncthreads();
    }

    // epilogue
    #pragma unroll
    for (int i = 0; i < 8; i++) {
        int m = m0 + ((i < 4) ? (ty*4 + i) : (64 + ty*4 + i - 4));
        #pragma unroll
        for (int half = 0; half < 2; half++) {
            int col = n0 + half*64 + tx*4;
            float4 v;
            v.x = acc[i][half*4+0]; v.y = acc[i][half*4+1];
            v.z = acc[i][half*4+2]; v.w = acc[i][half*4+3];
            if (MODE == 0) {
                // scatter into [s][b][h][n][d]
                int s   = col >> 10;
                int rem = col & 1023;
                int h   = rem >> 6;
                int d   = rem & 63;
                int b   = m >> 11;          // m / N_
                int nt  = m & (N_ - 1);
                size_t dst = (size_t)s * BHND +
                             ((((size_t)b * H_ + h) * N_ + nt) * D_ + d);
                *(float4*)&g_qkv[dst] = v;
            } else {
                float4 bb = *(const float4*)&bias[col];
                v.x += bb.x; v.y += bb.y; v.z += bb.z; v.w += bb.w;
                *(float4*)&Cout[(size_t)m * Nc + col] = v;
            }
        }
    }
}

// ----------------------------------------------------------------------------
// Flash attention, fp32. One thread = one query row (q[64], o[64] in regs,
// thread-local online softmax). Block = 128 threads = 128 query rows.
// Key/value tiles of 32 staged in shared memory.
// ----------------------------------------------------------------------------
__global__ __launch_bounds__(128) void flash_kernel()
{
    __shared__ float Ks[32][64];
    __shared__ float Vs[32][64];
    __shared__ float Sc[32][128];   // scores [key][thread]

    const int tid = threadIdx.x;
    const int b = blockIdx.z;
    const int h = blockIdx.y;
    const int q = blockIdx.x * 128 + tid;

    const float* Qp    = g_qkv + (((size_t)b * H_ + h) * N_ + q) * D_;
    const float* Kbase = g_qkv + (size_t)BHND     + (((size_t)b * H_ + h) * N_) * D_;
    const float* Vbase = g_qkv + (size_t)2 * BHND + (((size_t)b * H_ + h) * N_) * D_;

    float4 qv[16];
    #pragma unroll
    for (int i = 0; i < 16; i++) qv[i] = *(const float4*)&Qp[i * 4];

    float o[64];
    #pragma unroll
    for (int d = 0; d < 64; d++) o[d] = 0.f;

    float mR = -1e30f, l = 0.f;
    const float scale = 0.125f;   // D^-0.5

    for (int j0 = 0; j0 < N_; j0 += 32) {
        // load K/V tiles: 512 float4 each, 128 threads x 4
        #pragma unroll
        for (int i = 0; i < 4; i++) {
            int lin = tid + i * 128;     // 0..511
            int row = lin >> 4;          // 0..31
            int c4  = lin & 15;          // 0..15
            *(float4*)&Ks[row][c4*4] = *(const float4*)&Kbase[(size_t)(j0 + row) * 64 + c4*4];
            *(float4*)&Vs[row][c4*4] = *(const float4*)&Vbase[(size_t)(j0 + row) * 64 + c4*4];
        }
        __syncthreads();

        // pass 1: scores + tile max
        float tmax = -1e30f;
        for (int j = 0; j < 32; j++) {
            float s = 0.f;
            #pragma unroll
            for (int d4 = 0; d4 < 16; d4++) {
                float4 kv = *(float4*)&Ks[j][d4*4];
                s = fmaf(qv[d4].x, kv.x, s);
                s = fmaf(qv[d4].y, kv.y, s);
                s = fmaf(qv[d4].z, kv.z, s);
                s = fmaf(qv[d4].w, kv.w, s);
            }
            s *= scale;
            Sc[j][tid] = s;
            tmax = fmaxf(tmax, s);
        }

        float mnew = fmaxf(mR, tmax);
        float corr = __expf(mR - mnew);
        l *= corr;
        #pragma unroll
        for (int d = 0; d < 64; d++) o[d] *= corr;

        // pass 2: exp + PV accumulate
        for (int j = 0; j < 32; j++) {
            float p = __expf(Sc[j][tid] - mnew);
            l += p;
            #pragma unroll
            for (int d4 = 0; d4 < 16; d4++) {
                float4 vv = *(float4*)&Vs[j][d4*4];
                o[d4*4+0] = fmaf(p, vv.x, o[d4*4+0]);
                o[d4*4+1] = fmaf(p, vv.y, o[d4*4+1]);
                o[d4*4+2] = fmaf(p, vv.z, o[d4*4+2]);
                o[d4*4+3] = fmaf(p, vv.w, o[d4*4+3]);
            }
        }
        mR = mnew;
        __syncthreads();
    }

    const float inv = 1.f / l;
    float* dst = g_attn + ((size_t)b * N_ + q) * C_ + (size_t)h * D_;
    #pragma unroll
    for (int d4 = 0; d4 < 16; d4++) {
        float4 w;
        w.x = o[d4*4+0] * inv; w.y = o[d4*4+1] * inv;
        w.z = o[d4*4+2] * inv; w.w = o[d4*4+3] * inv;
        *(float4*)&dst[d4*4] = w;
    }
}

// ----------------------------------------------------------------------------
extern "C" void kernel_launch(void* const* d_in, const int* in_sizes, int n_in,
                              void* d_out, int out_size)
{
    const float* x      = (const float*)d_in[0];   // [B,N,C]
    const float* W_qkv  = (const float*)d_in[1];   // [3C,C]
    const float* W_proj = (const float*)d_in[2];   // [C,C]
    const float* b_proj = (const float*)d_in[3];   // [C]
    float* out = (float*)d_out;                    // [B,N,C]

    // 1) QKV projection -> g_qkv
    gemm_nt<0><<<dim3(3*C_/128, M_/128), 256>>>(x, W_qkv, nullptr, nullptr,
                                                M_, 3*C_, C_);
    // 2) flash attention -> g_attn
    flash_kernel<<<dim3(N_/128, H_, B_), 128>>>();
    // 3) output projection + bias -> d_out
    gemm_nt<1><<<dim3(C_/128, M_/128), 256>>>(nullptr, W_proj, b_proj, out,
                                              M_, C_, C_);
}

// round 2
// speedup vs baseline: 1.3037x; 1.3037x over previous
#include <cuda_runtime.h>
#include <cstdint>

#define B_ 4
#define N_ 2048
#define C_ 1024
#define H_ 16
#define D_ 64
#define M_ (B_*N_)              // 8192 tokens
#define BHND (B_*H_*N_*D_)      // 8388608 elements per Q/K/V tensor

// Scratch (alloc-free rule: __device__ globals)
__device__ float g_qkv[(size_t)3*BHND];      // [s][b][h][n][d]
__device__ float g_attn[(size_t)M_*C_];      // [b*N+n][h*D+d]

__device__ __forceinline__ uint32_t f2tf(float x) {
    uint32_t r; asm("cvt.rna.tf32.f32 %0, %1;" : "=r"(r) : "f"(x)); return r;
}

// ----------------------------------------------------------------------------
// tf32 tensor-core GEMM: C = A @ W^T (+bias). A [M,K] rm, W [Nc,K] rm.
// 128x128x16 block tile, 256 threads (8 warps as 2m x 4n), warp tile 64x32.
// mma.sync.m16n8k8.row.col tf32. Double-buffered smem, stride-20 padding
// (conflict-free fragment reads, 16B-aligned stores).
// MODE 0: A = x, epilogue scatters into g_qkv [s][b][h][n][d]
// MODE 1: A = g_attn, epilogue adds bias, writes Cout
// ----------------------------------------------------------------------------
template<int MODE>
__global__ __launch_bounds__(256) void gemm_tf32(const float* __restrict__ A,
                                                 const float* __restrict__ W,
                                                 const float* __restrict__ bias,
                                                 float* __restrict__ Cout,
                                                 int M, int Nc, int K)
{
    __shared__ uint32_t As[2][128][20];
    __shared__ uint32_t Bs[2][128][20];

    const int tid  = threadIdx.x;
    const int warp = tid >> 5;
    const int lane = tid & 31;
    const int g    = lane >> 2;      // group 0..7
    const int tg   = lane & 3;       // thread-in-group 0..3
    const int warpM = (warp >> 2) * 64;
    const int warpN = (warp & 3) * 32;
    const int m0 = blockIdx.y * 128;
    const int n0 = blockIdx.x * 128;

    const float* Ap = (MODE == 1) ? g_attn : A;

    float acc[4][4][4];
    #pragma unroll
    for (int i = 0; i < 4; i++)
        #pragma unroll
        for (int j = 0; j < 4; j++)
            #pragma unroll
            for (int c = 0; c < 4; c++) acc[i][j][c] = 0.f;

    float4 ra[2], rb[2];

    // gmem tile load into regs (A: 128x16 fp32 = 512 float4; same for B)
    auto loadG = [&](int k0) {
        #pragma unroll
        for (int i = 0; i < 2; i++) {
            int lin = tid + i * 256;
            int row = lin >> 2;
            int c4  = lin & 3;
            ra[i] = *(const float4*)&Ap[(size_t)(m0 + row) * K + k0 + c4 * 4];
            rb[i] = *(const float4*)&W [(size_t)(n0 + row) * K + k0 + c4 * 4];
        }
    };
    // reg -> smem with tf32 round-to-nearest conversion
    auto stS = [&](int buf) {
        #pragma unroll
        for (int i = 0; i < 2; i++) {
            int lin = tid + i * 256;
            int row = lin >> 2;
            int c4  = lin & 3;
            uint4 ua = make_uint4(f2tf(ra[i].x), f2tf(ra[i].y), f2tf(ra[i].z), f2tf(ra[i].w));
            *(uint4*)&As[buf][row][c4 * 4] = ua;
            uint4 ub = make_uint4(f2tf(rb[i].x), f2tf(rb[i].y), f2tf(rb[i].z), f2tf(rb[i].w));
            *(uint4*)&Bs[buf][row][c4 * 4] = ub;
        }
    };

    loadG(0);
    stS(0);
    __syncthreads();

    int buf = 0;
    for (int k0 = 0; k0 < K; k0 += 16) {
        const bool next = (k0 + 16) < K;
        if (next) loadG(k0 + 16);

        #pragma unroll
        for (int kk = 0; kk < 2; kk++) {
            const int k = kk * 8;
            uint32_t af[4][4], bf[4][2];
            #pragma unroll
            for (int mt = 0; mt < 4; mt++) {
                int m = warpM + mt * 16;
                af[mt][0] = As[buf][m + g    ][k + tg];
                af[mt][1] = As[buf][m + g + 8][k + tg];
                af[mt][2] = As[buf][m + g    ][k + tg + 4];
                af[mt][3] = As[buf][m + g + 8][k + tg + 4];
            }
            #pragma unroll
            for (int nt = 0; nt < 4; nt++) {
                int n = warpN + nt * 8;
                bf[nt][0] = Bs[buf][n + g][k + tg];
                bf[nt][1] = Bs[buf][n + g][k + tg + 4];
            }
            #pragma unroll
            for (int mt = 0; mt < 4; mt++)
                #pragma unroll
                for (int nt = 0; nt < 4; nt++) {
                    float* c = acc[mt][nt];
                    asm volatile(
                        "mma.sync.aligned.m16n8k8.row.col.f32.tf32.tf32.f32 "
                        "{%0,%1,%2,%3}, {%4,%5,%6,%7}, {%8,%9}, {%0,%1,%2,%3};"
                        : "+f"(c[0]), "+f"(c[1]), "+f"(c[2]), "+f"(c[3])
                        : "r"(af[mt][0]), "r"(af[mt][1]), "r"(af[mt][2]), "r"(af[mt][3]),
                          "r"(bf[nt][0]), "r"(bf[nt][1]));
                }
        }

        if (next) stS(buf ^ 1);
        __syncthreads();
        buf ^= 1;
    }

    // epilogue: each thread owns 2 rows x 2 cols per (mt,nt) fragment
    #pragma unroll
    for (int mt = 0; mt < 4; mt++) {
        #pragma unroll
        for (int r = 0; r < 2; r++) {
            int m = m0 + warpM + mt * 16 + g + r * 8;
            #pragma unroll
            for (int nt = 0; nt < 4; nt++) {
                int col = n0 + warpN + nt * 8 + tg * 2;
                float2 v;
                v.x = acc[mt][nt][r * 2 + 0];
                v.y = acc[mt][nt][r * 2 + 1];
                if (MODE == 0) {
                    int s   = col >> 10;
                    int rem = col & 1023;
                    int h   = rem >> 6;
                    int d   = rem & 63;
                    int b   = m >> 11;
                    int ntk = m & (N_ - 1);
                    size_t dst = (size_t)s * BHND +
                                 ((((size_t)b * H_ + h) * N_ + ntk) * D_ + d);
                    *(float2*)&g_qkv[dst] = v;
                } else {
                    float2 bb = *(const float2*)&bias[col];
                    v.x += bb.x; v.y += bb.y;
                    *(float2*)&Cout[(size_t)m * Nc + col] = v;
                }
            }
        }
    }
}

// ----------------------------------------------------------------------------
// Flash attention, fp32. One thread = one query row (q[64], o[64] in regs,
// thread-local online softmax). Block = 128 threads = 128 query rows.
// ----------------------------------------------------------------------------
__global__ __launch_bounds__(128) void flash_kernel()
{
    __shared__ float Ks[32][64];
    __shared__ float Vs[32][64];
    __shared__ float Sc[32][128];

    const int tid = threadIdx.x;
    const int b = blockIdx.z;
    const int h = blockIdx.y;
    const int q = blockIdx.x * 128 + tid;

    const float* Qp    = g_qkv + (((size_t)b * H_ + h) * N_ + q) * D_;
    const float* Kbase = g_qkv + (size_t)BHND     + (((size_t)b * H_ + h) * N_) * D_;
    const float* Vbase = g_qkv + (size_t)2 * BHND + (((size_t)b * H_ + h) * N_) * D_;

    float4 qv[16];
    #pragma unroll
    for (int i = 0; i < 16; i++) qv[i] = *(const float4*)&Qp[i * 4];

    float o[64];
    #pragma unroll
    for (int d = 0; d < 64; d++) o[d] = 0.f;

    float mR = -1e30f, l = 0.f;
    const float scale = 0.125f;

    for (int j0 = 0; j0 < N_; j0 += 32) {
        #pragma unroll
        for (int i = 0; i < 4; i++) {
            int lin = tid + i * 128;
            int row = lin >> 4;
            int c4  = lin & 15;
            *(float4*)&Ks[row][c4*4] = *(const float4*)&Kbase[(size_t)(j0 + row) * 64 + c4*4];
            *(float4*)&Vs[row][c4*4] = *(const float4*)&Vbase[(size_t)(j0 + row) * 64 + c4*4];
        }
        __syncthreads();

        float tmax = -1e30f;
        for (int j = 0; j < 32; j++) {
            float s = 0.f;
            #pragma unroll
            for (int d4 = 0; d4 < 16; d4++) {
                float4 kv = *(float4*)&Ks[j][d4*4];
                s = fmaf(qv[d4].x, kv.x, s);
                s = fmaf(qv[d4].y, kv.y, s);
                s = fmaf(qv[d4].z, kv.z, s);
                s = fmaf(qv[d4].w, kv.w, s);
            }
            s *= scale;
            Sc[j][tid] = s;
            tmax = fmaxf(tmax, s);
        }

        float mnew = fmaxf(mR, tmax);
        float corr = __expf(mR - mnew);
        l *= corr;
        #pragma unroll
        for (int d = 0; d < 64; d++) o[d] *= corr;

        for (int j = 0; j < 32; j++) {
            float p = __expf(Sc[j][tid] - mnew);
            l += p;
            #pragma unroll
            for (int d4 = 0; d4 < 16; d4++) {
                float4 vv = *(float4*)&Vs[j][d4*4];
                o[d4*4+0] = fmaf(p, vv.x, o[d4*4+0]);
                o[d4*4+1] = fmaf(p, vv.y, o[d4*4+1]);
                o[d4*4+2] = fmaf(p, vv.z, o[d4*4+2]);
                o[d4*4+3] = fmaf(p, vv.w, o[d4*4+3]);
            }
        }
        mR = mnew;
        __syncthreads();
    }

    const float inv = 1.f / l;
    float* dst = g_attn + ((size_t)b * N_ + q) * C_ + (size_t)h * D_;
    #pragma unroll
    for (int d4 = 0; d4 < 16; d4++) {
        float4 w;
        w.x = o[d4*4+0] * inv; w.y = o[d4*4+1] * inv;
        w.z = o[d4*4+2] * inv; w.w = o[d4*4+3] * inv;
        *(float4*)&dst[d4*4] = w;
    }
}

// ----------------------------------------------------------------------------
extern "C" void kernel_launch(void* const* d_in, const int* in_sizes, int n_in,
                              void* d_out, int out_size)
{
    const float* x      = (const float*)d_in[0];   // [B,N,C]
    const float* W_qkv  = (const float*)d_in[1];   // [3C,C]
    const float* W_proj = (const float*)d_in[2];   // [C,C]
    const float* b_proj = (const float*)d_in[3];   // [C]
    float* out = (float*)d_out;                    // [B,N,C]

    gemm_tf32<0><<<dim3(3*C_/128, M_/128), 256>>>(x, W_qkv, nullptr, nullptr,
                                                  M_, 3*C_, C_);
    flash_kernel<<<dim3(N_/128, H_, B_), 128>>>();
    gemm_tf32<1><<<dim3(C_/128, M_/128), 256>>>(nullptr, W_proj, b_proj, out,
                                                M_, C_, C_);
}

// round 3
// speedup vs baseline: 2.5312x; 1.9415x over previous
#include <cuda_runtime.h>
#include <cstdint>

#define B_ 4
#define N_ 2048
#define C_ 1024
#define H_ 16
#define D_ 64
#define M_ (B_*N_)              // 8192 tokens
#define BHND (B_*H_*N_*D_)      // 8388608 elements per Q/K/V tensor

// Scratch (alloc-free rule: __device__ globals)
__device__ float g_qkv[(size_t)3*BHND];      // [s][b][h][n][d]
__device__ float g_attn[(size_t)M_*C_];      // [b*N+n][h*D+d]

__device__ __forceinline__ uint32_t f2tf(float x) {
    uint32_t r; asm("cvt.rna.tf32.f32 %0, %1;" : "=r"(r) : "f"(x)); return r;
}
__device__ __forceinline__ float tf2f(uint32_t x) { return __uint_as_float(x); }

__device__ __forceinline__ void mma_tf32(float* c, const uint32_t* a,
                                         uint32_t b0, uint32_t b1) {
    asm volatile(
        "mma.sync.aligned.m16n8k8.row.col.f32.tf32.tf32.f32 "
        "{%0,%1,%2,%3}, {%4,%5,%6,%7}, {%8,%9}, {%0,%1,%2,%3};"
        : "+f"(c[0]), "+f"(c[1]), "+f"(c[2]), "+f"(c[3])
        : "r"(a[0]), "r"(a[1]), "r"(a[2]), "r"(a[3]), "r"(b0), "r"(b1));
}

// ----------------------------------------------------------------------------
// tf32 tensor-core GEMM: C = A @ W^T (+bias). (unchanged from round 2)
// ----------------------------------------------------------------------------
template<int MODE>
__global__ __launch_bounds__(256) void gemm_tf32(const float* __restrict__ A,
                                                 const float* __restrict__ W,
                                                 const float* __restrict__ bias,
                                                 float* __restrict__ Cout,
                                                 int M, int Nc, int K)
{
    __shared__ uint32_t As[2][128][20];
    __shared__ uint32_t Bs[2][128][20];

    const int tid  = threadIdx.x;
    const int warp = tid >> 5;
    const int lane = tid & 31;
    const int g    = lane >> 2;
    const int tg   = lane & 3;
    const int warpM = (warp >> 2) * 64;
    const int warpN = (warp & 3) * 32;
    const int m0 = blockIdx.y * 128;
    const int n0 = blockIdx.x * 128;

    const float* Ap = (MODE == 1) ? g_attn : A;

    float acc[4][4][4];
    #pragma unroll
    for (int i = 0; i < 4; i++)
        #pragma unroll
        for (int j = 0; j < 4; j++)
            #pragma unroll
            for (int c = 0; c < 4; c++) acc[i][j][c] = 0.f;

    float4 ra[2], rb[2];

    auto loadG = [&](int k0) {
        #pragma unroll
        for (int i = 0; i < 2; i++) {
            int lin = tid + i * 256;
            int row = lin >> 2;
            int c4  = lin & 3;
            ra[i] = *(const float4*)&Ap[(size_t)(m0 + row) * K + k0 + c4 * 4];
            rb[i] = *(const float4*)&W [(size_t)(n0 + row) * K + k0 + c4 * 4];
        }
    };
    auto stS = [&](int buf) {
        #pragma unroll
        for (int i = 0; i < 2; i++) {
            int lin = tid + i * 256;
            int row = lin >> 2;
            int c4  = lin & 3;
            uint4 ua = make_uint4(f2tf(ra[i].x), f2tf(ra[i].y), f2tf(ra[i].z), f2tf(ra[i].w));
            *(uint4*)&As[buf][row][c4 * 4] = ua;
            uint4 ub = make_uint4(f2tf(rb[i].x), f2tf(rb[i].y), f2tf(rb[i].z), f2tf(rb[i].w));
            *(uint4*)&Bs[buf][row][c4 * 4] = ub;
        }
    };

    loadG(0);
    stS(0);
    __syncthreads();

    int buf = 0;
    for (int k0 = 0; k0 < K; k0 += 16) {
        const bool next = (k0 + 16) < K;
        if (next) loadG(k0 + 16);

        #pragma unroll
        for (int kk = 0; kk < 2; kk++) {
            const int k = kk * 8;
            uint32_t af[4][4], bf[4][2];
            #pragma unroll
            for (int mt = 0; mt < 4; mt++) {
                int m = warpM + mt * 16;
                af[mt][0] = As[buf][m + g    ][k + tg];
                af[mt][1] = As[buf][m + g + 8][k + tg];
                af[mt][2] = As[buf][m + g    ][k + tg + 4];
                af[mt][3] = As[buf][m + g + 8][k + tg + 4];
            }
            #pragma unroll
            for (int nt = 0; nt < 4; nt++) {
                int n = warpN + nt * 8;
                bf[nt][0] = Bs[buf][n + g][k + tg];
                bf[nt][1] = Bs[buf][n + g][k + tg + 4];
            }
            #pragma unroll
            for (int mt = 0; mt < 4; mt++)
                #pragma unroll
                for (int nt = 0; nt < 4; nt++)
                    mma_tf32(acc[mt][nt], af[mt], bf[nt][0], bf[nt][1]);
        }

        if (next) stS(buf ^ 1);
        __syncthreads();
        buf ^= 1;
    }

    #pragma unroll
    for (int mt = 0; mt < 4; mt++) {
        #pragma unroll
        for (int r = 0; r < 2; r++) {
            int m = m0 + warpM + mt * 16 + g + r * 8;
            #pragma unroll
            for (int nt = 0; nt < 4; nt++) {
                int col = n0 + warpN + nt * 8 + tg * 2;
                float2 v;
                v.x = acc[mt][nt][r * 2 + 0];
                v.y = acc[mt][nt][r * 2 + 1];
                if (MODE == 0) {
                    int s   = col >> 10;
                    int rem = col & 1023;
                    int h   = rem >> 6;
                    int d   = rem & 63;
                    int b   = m >> 11;
                    int ntk = m & (N_ - 1);
                    size_t dst = (size_t)s * BHND +
                                 ((((size_t)b * H_ + h) * N_ + ntk) * D_ + d);
                    *(float2*)&g_qkv[dst] = v;
                } else {
                    float2 bb = *(const float2*)&bias[col];
                    v.x += bb.x; v.y += bb.y;
                    *(float2*)&Cout[(size_t)m * Nc + col] = v;
                }
            }
        }
    }
}

// ----------------------------------------------------------------------------
// Tensor-core flash attention (tf32 with split-Q and split-P).
// Block: 256 threads = 8 warps; each warp owns 16 query rows; one (b,h)/block.
// Key tiles of 64. S = (q_hi+q_lo) K^T (2 mmas), O += (p_hi+p_lo) V (2 mmas).
// Dynamic smem: Ks[64][68] | Vs[64][68] | P[8 warps][16][132] (hi col 0..63,
// lo col 66..129).
// ----------------------------------------------------------------------------
#define KS_STRIDE 68
#define P_STRIDE  132

__global__ __launch_bounds__(256, 1) void flash_tc()
{
    extern __shared__ float sm[];
    float* Ks = sm;                       // 64*68
    float* Vs = sm + 64 * KS_STRIDE;      // 64*68
    float* Pb = sm + 2 * 64 * KS_STRIDE;  // 8*16*132

    const int tid  = threadIdx.x;
    const int warp = tid >> 5;
    const int lane = tid & 31;
    const int g    = lane >> 2;
    const int tg   = lane & 3;

    const int b = blockIdx.z;
    const int h = blockIdx.y;
    const int q0 = blockIdx.x * 128 + warp * 16;   // warp's first query row

    const float* Qp    = g_qkv + (((size_t)b * H_ + h) * N_ + q0) * D_;
    const float* Kbase = g_qkv + (size_t)BHND     + (((size_t)b * H_ + h) * N_) * D_;
    const float* Vbase = g_qkv + (size_t)2 * BHND + (((size_t)b * H_ + h) * N_) * D_;

    float* Pw = Pb + warp * 16 * P_STRIDE;

    // Load Q fragments (pre-scaled by D^-0.5 = 0.125, exact), split hi/lo
    uint32_t qh[8][4], ql[8][4];
    #pragma unroll
    for (int kk = 0; kk < 8; kk++) {
        float v0 = Qp[(size_t)g       * 64 + kk * 8 + tg    ] * 0.125f;
        float v1 = Qp[(size_t)(g + 8) * 64 + kk * 8 + tg    ] * 0.125f;
        float v2 = Qp[(size_t)g       * 64 + kk * 8 + tg + 4] * 0.125f;
        float v3 = Qp[(size_t)(g + 8) * 64 + kk * 8 + tg + 4] * 0.125f;
        qh[kk][0] = f2tf(v0); ql[kk][0] = f2tf(v0 - tf2f(qh[kk][0]));
        qh[kk][1] = f2tf(v1); ql[kk][1] = f2tf(v1 - tf2f(qh[kk][1]));
        qh[kk][2] = f2tf(v2); ql[kk][2] = f2tf(v2 - tf2f(qh[kk][2]));
        qh[kk][3] = f2tf(v3); ql[kk][3] = f2tf(v3 - tf2f(qh[kk][3]));
    }

    float o[8][4];
    #pragma unroll
    for (int nt = 0; nt < 8; nt++)
        #pragma unroll
        for (int c = 0; c < 4; c++) o[nt][c] = 0.f;

    float m0 = -1e30f, m1 = -1e30f, l0 = 0.f, l1 = 0.f;

    for (int j0 = 0; j0 < N_; j0 += 64) {
        __syncthreads();   // prev iter's PV reads done before overwriting K/V
        // load K/V tile (64x64), converting to tf32 (rna)
        #pragma unroll
        for (int i = 0; i < 4; i++) {
            int lin = tid + i * 256;     // 0..1023
            int row = lin >> 4;          // 0..63
            int c4  = lin & 15;          // 0..15
            float4 kv = *(const float4*)&Kbase[(size_t)(j0 + row) * 64 + c4 * 4];
            uint4 ku = make_uint4(f2tf(kv.x), f2tf(kv.y), f2tf(kv.z), f2tf(kv.w));
            *(uint4*)&Ks[row * KS_STRIDE + c4 * 4] = ku;
            float4 vv = *(const float4*)&Vbase[(size_t)(j0 + row) * 64 + c4 * 4];
            uint4 vu = make_uint4(f2tf(vv.x), f2tf(vv.y), f2tf(vv.z), f2tf(vv.w));
            *(uint4*)&Vs[row * KS_STRIDE + c4 * 4] = vu;
        }
        __syncthreads();

        // S = Q K^T  (split-Q: 2 mmas per step)
        float sc[8][4];
        #pragma unroll
        for (int nt = 0; nt < 8; nt++)
            #pragma unroll
            for (int c = 0; c < 4; c++) sc[nt][c] = 0.f;

        #pragma unroll
        for (int kk = 0; kk < 8; kk++) {
            #pragma unroll
            for (int nt = 0; nt < 8; nt++) {
                uint32_t b0 = __float_as_uint(Ks[(nt * 8 + g) * KS_STRIDE + kk * 8 + tg    ]);
                uint32_t b1 = __float_as_uint(Ks[(nt * 8 + g) * KS_STRIDE + kk * 8 + tg + 4]);
                mma_tf32(sc[nt], qh[kk], b0, b1);
                mma_tf32(sc[nt], ql[kk], b0, b1);
            }
        }

        // online softmax (rows g and g+8)
        float tm0 = -1e30f, tm1 = -1e30f;
        #pragma unroll
        for (int nt = 0; nt < 8; nt++) {
            tm0 = fmaxf(tm0, fmaxf(sc[nt][0], sc[nt][1]));
            tm1 = fmaxf(tm1, fmaxf(sc[nt][2], sc[nt][3]));
        }
        tm0 = fmaxf(tm0, __shfl_xor_sync(0xffffffffu, tm0, 1));
        tm0 = fmaxf(tm0, __shfl_xor_sync(0xffffffffu, tm0, 2));
        tm1 = fmaxf(tm1, __shfl_xor_sync(0xffffffffu, tm1, 1));
        tm1 = fmaxf(tm1, __shfl_xor_sync(0xffffffffu, tm1, 2));

        float m0n = fmaxf(m0, tm0);
        float m1n = fmaxf(m1, tm1);
        float cr0 = __expf(m0 - m0n);
        float cr1 = __expf(m1 - m1n);

        float rs0 = 0.f, rs1 = 0.f;
        #pragma unroll
        for (int nt = 0; nt < 8; nt++) {
            float p0 = __expf(sc[nt][0] - m0n);
            float p1 = __expf(sc[nt][1] - m0n);
            float p2 = __expf(sc[nt][2] - m1n);
            float p3 = __expf(sc[nt][3] - m1n);
            rs0 += p0 + p1;
            rs1 += p2 + p3;
            uint32_t h0 = f2tf(p0), h1 = f2tf(p1), h2 = f2tf(p2), h3 = f2tf(p3);
            float l0v = p0 - tf2f(h0), l1v = p1 - tf2f(h1);
            float l2v = p2 - tf2f(h2), l3v = p3 - tf2f(h3);
            int col = nt * 8 + 2 * tg;
            *(float2*)&Pw[(size_t)g * P_STRIDE + col]            = make_float2(tf2f(h0), tf2f(h1));
            *(float2*)&Pw[(size_t)g * P_STRIDE + 66 + col]       = make_float2(tf2f(f2tf(l0v)), tf2f(f2tf(l1v)));
            *(float2*)&Pw[(size_t)(g + 8) * P_STRIDE + col]      = make_float2(tf2f(h2), tf2f(h3));
            *(float2*)&Pw[(size_t)(g + 8) * P_STRIDE + 66 + col] = make_float2(tf2f(f2tf(l2v)), tf2f(f2tf(l3v)));
        }
        rs0 += __shfl_xor_sync(0xffffffffu, rs0, 1);
        rs0 += __shfl_xor_sync(0xffffffffu, rs0, 2);
        rs1 += __shfl_xor_sync(0xffffffffu, rs1, 1);
        rs1 += __shfl_xor_sync(0xffffffffu, rs1, 2);

        l0 = l0 * cr0 + rs0;
        l1 = l1 * cr1 + rs1;
        m0 = m0n; m1 = m1n;
        #pragma unroll
        for (int nt = 0; nt < 8; nt++) {
            o[nt][0] *= cr0; o[nt][1] *= cr0;
            o[nt][2] *= cr1; o[nt][3] *= cr1;
        }

        __syncwarp();

        // O += P V  (split-P: 2 mmas per step)
        #pragma unroll
        for (int kk = 0; kk < 8; kk++) {
            uint32_t ah[4], al[4];
            ah[0] = __float_as_uint(Pw[(size_t)g       * P_STRIDE + kk * 8 + tg    ]);
            ah[1] = __float_as_uint(Pw[(size_t)(g + 8) * P_STRIDE + kk * 8 + tg    ]);
            ah[2] = __float_as_uint(Pw[(size_t)g       * P_STRIDE + kk * 8 + tg + 4]);
            ah[3] = __float_as_uint(Pw[(size_t)(g + 8) * P_STRIDE + kk * 8 + tg + 4]);
            al[0] = __float_as_uint(Pw[(size_t)g       * P_STRIDE + 66 + kk * 8 + tg    ]);
            al[1] = __float_as_uint(Pw[(size_t)(g + 8) * P_STRIDE + 66 + kk * 8 + tg    ]);
            al[2] = __float_as_uint(Pw[(size_t)g       * P_STRIDE + 66 + kk * 8 + tg + 4]);
            al[3] = __float_as_uint(Pw[(size_t)(g + 8) * P_STRIDE + 66 + kk * 8 + tg + 4]);
            #pragma unroll
            for (int nt = 0; nt < 8; nt++) {
                uint32_t b0 = __float_as_uint(Vs[(kk * 8 + tg    ) * KS_STRIDE + nt * 8 + g]);
                uint32_t b1 = __float_as_uint(Vs[(kk * 8 + tg + 4) * KS_STRIDE + nt * 8 + g]);
                mma_tf32(o[nt], ah, b0, b1);
                mma_tf32(o[nt], al, b0, b1);
            }
        }
    }

    // write out: g_attn[b*N+q][h*64+d]
    const float inv0 = 1.f / l0;
    const float inv1 = 1.f / l1;
    float* d0 = g_attn + ((size_t)b * N_ + q0 + g    ) * C_ + (size_t)h * 64;
    float* d1 = g_attn + ((size_t)b * N_ + q0 + g + 8) * C_ + (size_t)h * 64;
    #pragma unroll
    for (int nt = 0; nt < 8; nt++) {
        int col = nt * 8 + 2 * tg;
        *(float2*)&d0[col] = make_float2(o[nt][0] * inv0, o[nt][1] * inv0);
        *(float2*)&d1[col] = make_float2(o[nt][2] * inv1, o[nt][3] * inv1);
    }
}

// ----------------------------------------------------------------------------
extern "C" void kernel_launch(void* const* d_in, const int* in_sizes, int n_in,
                              void* d_out, int out_size)
{
    const float* x      = (const float*)d_in[0];   // [B,N,C]
    const float* W_qkv  = (const float*)d_in[1];   // [3C,C]
    const float* W_proj = (const float*)d_in[2];   // [C,C]
    const float* b_proj = (const float*)d_in[3];   // [C]
    float* out = (float*)d_out;                    // [B,N,C]

    const int FLASH_SMEM = (2 * 64 * KS_STRIDE + 8 * 16 * P_STRIDE) * 4; // 102400
    cudaFuncSetAttribute(flash_tc, cudaFuncAttributeMaxDynamicSharedMemorySize,
                         FLASH_SMEM);

    gemm_tf32<0><<<dim3(3*C_/128, M_/128), 256>>>(x, W_qkv, nullptr, nullptr,
                                                  M_, 3*C_, C_);
    flash_tc<<<dim3(N_/128, H_, B_), 256, FLASH_SMEM>>>();
    gemm_tf32<1><<<dim3(C_/128, M_/128), 256>>>(nullptr, W_proj, b_proj, out,
                                                M_, C_, C_);
}

// round 6
// speedup vs baseline: 3.1341x; 1.2382x over previous
#include <cuda_runtime.h>
#include <cuda_fp16.h>
#include <cstdint>

#define B_ 4
#define N_ 2048
#define C_ 1024
#define H_ 16
#define D_ 64
#define M_ (B_*N_)              // 8192 tokens
#define BHND (B_*H_*N_*D_)      // 8388608 elements per Q/K/V tensor

// Scratch (alloc-free rule: __device__ globals)
__device__ float g_qkv[(size_t)3*BHND];      // [s][b][h][n][d]
__device__ float g_attn[(size_t)M_*C_];      // [b*N+n][h*D+d]

// ---------------------------------------------------------------- helpers ---
__device__ __forceinline__ uint32_t f2tf(float x) {
    uint32_t r; asm("cvt.rna.tf32.f32 %0, %1;" : "=r"(r) : "f"(x)); return r;
}

__device__ __forceinline__ void mma_tf32(float* c, const uint32_t* a,
                                         uint32_t b0, uint32_t b1) {
    asm volatile(
        "mma.sync.aligned.m16n8k8.row.col.f32.tf32.tf32.f32 "
        "{%0,%1,%2,%3}, {%4,%5,%6,%7}, {%8,%9}, {%0,%1,%2,%3};"
        : "+f"(c[0]), "+f"(c[1]), "+f"(c[2]), "+f"(c[3])
        : "r"(a[0]), "r"(a[1]), "r"(a[2]), "r"(a[3]), "r"(b0), "r"(b1));
}

__device__ __forceinline__ void mma_f16(float* c, const uint32_t* a,
                                        uint32_t b0, uint32_t b1) {
    asm volatile(
        "mma.sync.aligned.m16n8k16.row.col.f32.f16.f16.f32 "
        "{%0,%1,%2,%3}, {%4,%5,%6,%7}, {%8,%9}, {%0,%1,%2,%3};"
        : "+f"(c[0]), "+f"(c[1]), "+f"(c[2]), "+f"(c[3])
        : "r"(a[0]), "r"(a[1]), "r"(a[2]), "r"(a[3]), "r"(b0), "r"(b1));
}

__device__ __forceinline__ uint32_t smem_u32(const void* p) {
    uint32_t a;
    asm("{ .reg .u64 t; cvta.to.shared.u64 t, %1; cvt.u32.u64 %0, t; }"
        : "=r"(a) : "l"(p));
    return a;
}

#define LDSM_X2(r0, r1, addr) \
    asm volatile("ldmatrix.sync.aligned.m8n8.x2.shared.b16 {%0,%1}, [%2];" \
                 : "=r"(r0), "=r"(r1) : "r"(addr))
#define LDSM_X2T(r0, r1, addr) \
    asm volatile("ldmatrix.sync.aligned.m8n8.x2.trans.shared.b16 {%0,%1}, [%2];" \
                 : "=r"(r0), "=r"(r1) : "r"(addr))

__device__ __forceinline__ uint32_t pkh(__half a, __half b) {
    __half2 h = __halves2half2(a, b);
    return *(uint32_t*)&h;
}

// ----------------------------------------------------------------------------
// tf32 tensor-core GEMM: C = A @ W^T (+bias). (known-good from round 2/3)
// ----------------------------------------------------------------------------
template<int MODE>
__global__ __launch_bounds__(256) void gemm_tf32(const float* __restrict__ A,
                                                 const float* __restrict__ W,
                                                 const float* __restrict__ bias,
                                                 float* __restrict__ Cout,
                                                 int M, int Nc, int K)
{
    __shared__ uint32_t As[2][128][20];
    __shared__ uint32_t Bs[2][128][20];

    const int tid  = threadIdx.x;
    const int warp = tid >> 5;
    const int lane = tid & 31;
    const int g    = lane >> 2;
    const int tg   = lane & 3;
    const int warpM = (warp >> 2) * 64;
    const int warpN = (warp & 3) * 32;
    const int m0 = blockIdx.y * 128;
    const int n0 = blockIdx.x * 128;

    const float* Ap = (MODE == 1) ? g_attn : A;

    float acc[4][4][4];
    #pragma unroll
    for (int i = 0; i < 4; i++)
        #pragma unroll
        for (int j = 0; j < 4; j++)
            #pragma unroll
            for (int c = 0; c < 4; c++) acc[i][j][c] = 0.f;

    float4 ra[2], rb[2];

    auto loadG = [&](int k0) {
        #pragma unroll
        for (int i = 0; i < 2; i++) {
            int lin = tid + i * 256;
            int row = lin >> 2;
            int c4  = lin & 3;
            ra[i] = *(const float4*)&Ap[(size_t)(m0 + row) * K + k0 + c4 * 4];
            rb[i] = *(const float4*)&W [(size_t)(n0 + row) * K + k0 + c4 * 4];
        }
    };
    auto stS = [&](int buf) {
        #pragma unroll
        for (int i = 0; i < 2; i++) {
            int lin = tid + i * 256;
            int row = lin >> 2;
            int c4  = lin & 3;
            uint4 ua = make_uint4(f2tf(ra[i].x), f2tf(ra[i].y), f2tf(ra[i].z), f2tf(ra[i].w));
            *(uint4*)&As[buf][row][c4 * 4] = ua;
            uint4 ub = make_uint4(f2tf(rb[i].x), f2tf(rb[i].y), f2tf(rb[i].z), f2tf(rb[i].w));
            *(uint4*)&Bs[buf][row][c4 * 4] = ub;
        }
    };

    loadG(0);
    stS(0);
    __syncthreads();

    int buf = 0;
    for (int k0 = 0; k0 < K; k0 += 16) {
        const bool next = (k0 + 16) < K;
        if (next) loadG(k0 + 16);

        #pragma unroll
        for (int kk = 0; kk < 2; kk++) {
            const int k = kk * 8;
            uint32_t af[4][4], bf[4][2];
            #pragma unroll
            for (int mt = 0; mt < 4; mt++) {
                int m = warpM + mt * 16;
                af[mt][0] = As[buf][m + g    ][k + tg];
                af[mt][1] = As[buf][m + g + 8][k + tg];
                af[mt][2] = As[buf][m + g    ][k + tg + 4];
                af[mt][3] = As[buf][m + g + 8][k + tg + 4];
            }
            #pragma unroll
            for (int nt = 0; nt < 4; nt++) {
                int n = warpN + nt * 8;
                bf[nt][0] = Bs[buf][n + g][k + tg];
                bf[nt][1] = Bs[buf][n + g][k + tg + 4];
            }
            #pragma unroll
            for (int mt = 0; mt < 4; mt++)
                #pragma unroll
                for (int nt = 0; nt < 4; nt++)
                    mma_tf32(acc[mt][nt], af[mt], bf[nt][0], bf[nt][1]);
        }

        if (next) stS(buf ^ 1);
        __syncthreads();
        buf ^= 1;
    }

    #pragma unroll
    for (int mt = 0; mt < 4; mt++) {
        #pragma unroll
        for (int r = 0; r < 2; r++) {
            int m = m0 + warpM + mt * 16 + g + r * 8;
            #pragma unroll
            for (int nt = 0; nt < 4; nt++) {
                int col = n0 + warpN + nt * 8 + tg * 2;
                float2 v;
                v.x = acc[mt][nt][r * 2 + 0];
                v.y = acc[mt][nt][r * 2 + 1];
                if (MODE == 0) {
                    int s   = col >> 10;
                    int rem = col & 1023;
                    int h   = rem >> 6;
                    int d   = rem & 63;
                    int b   = m >> 11;
                    int ntk = m & (N_ - 1);
                    size_t dst = (size_t)s * BHND +
                                 ((((size_t)b * H_ + h) * N_ + ntk) * D_ + d);
                    *(float2*)&g_qkv[dst] = v;
                } else {
                    float2 bb = *(const float2*)&bias[col];
                    v.x += bb.x; v.y += bb.y;
                    *(float2*)&Cout[(size_t)m * Nc + col] = v;
                }
            }
        }
    }
}

// ----------------------------------------------------------------------------
// fp16-split tensor-core flash attention.
// Block: 256 threads = 8 warps; warp owns 16 query rows; one (b,h) per block.
// 64-key tiles. K/V converted fp32 -> (hi, lo) fp16 at tile load.
// S = qh·kh + qh·kl + ql·kh (m16n8k16), P repacked hi/lo register-only,
// O += ph·vh + ph·vl + pl·vh.  Smem stride 72 halves -> conflict-free ldmatrix.
// ----------------------------------------------------------------------------
#define KV_STRIDE 72           // halves per row

__global__ __launch_bounds__(256, 1) void flash_f16()
{
    __shared__ __half Kh[64 * KV_STRIDE];
    __shared__ __half Kl[64 * KV_STRIDE];
    __shared__ __half Vh[64 * KV_STRIDE];
    __shared__ __half Vl[64 * KV_STRIDE];

    const int tid  = threadIdx.x;
    const int warp = tid >> 5;
    const int lane = tid & 31;
    const int g    = lane >> 2;
    const int tg   = lane & 3;

    const int b = blockIdx.z;
    const int h = blockIdx.y;
    const int q0 = blockIdx.x * 128 + warp * 16;

    const float* Qp    = g_qkv + (((size_t)b * H_ + h) * N_ + q0) * D_;
    const float* Kbase = g_qkv + (size_t)BHND     + (((size_t)b * H_ + h) * N_) * D_;
    const float* Vbase = g_qkv + (size_t)2 * BHND + (((size_t)b * H_ + h) * N_) * D_;

    // per-lane ldmatrix base offsets (bytes)
    const uint32_t smKh = smem_u32(Kh), smKl = smem_u32(Kl);
    const uint32_t smVh = smem_u32(Vh), smVl = smem_u32(Vl);
    // K (non-trans): lane -> key row (lane&7), dim block ((lane>>3)&1)*8
    const uint32_t kOfs = (uint32_t)(((lane & 7) * KV_STRIDE + ((lane >> 3) & 1) * 8) * 2);
    // V (trans): lane -> key row (lane&15), dim col set per nt2
    const uint32_t vOfs = (uint32_t)((lane & 15) * KV_STRIDE * 2);

    // Load Q (scaled by D^-0.5 = 0.125), split into fp16 hi/lo A-fragments.
    // qh[kk][0]=(row g, d0,d0+1) [1]=(g+8, d0,d0+1) [2]=(g, d0+8,+9) [3]=(g+8, d0+8,+9)
    uint32_t qh[4][4], ql[4][4];
    #pragma unroll
    for (int kk = 0; kk < 4; kk++) {
        const int d0 = kk * 16 + 2 * tg;
        #pragma unroll
        for (int half8 = 0; half8 < 2; half8++) {
            #pragma unroll
            for (int r = 0; r < 2; r++) {
                float v0 = Qp[(size_t)(g + r * 8) * 64 + d0 + half8 * 8    ] * 0.125f;
                float v1 = Qp[(size_t)(g + r * 8) * 64 + d0 + half8 * 8 + 1] * 0.125f;
                __half h0 = __float2half_rn(v0), h1 = __float2half_rn(v1);
                __half l0 = __float2half_rn(v0 - __half2float(h0));
                __half l1 = __float2half_rn(v1 - __half2float(h1));
                qh[kk][half8 * 2 + r] = pkh(h0, h1);
                ql[kk][half8 * 2 + r] = pkh(l0, l1);
            }
        }
    }

    float o[8][4];
    #pragma unroll
    for (int nt = 0; nt < 8; nt++)
        #pragma unroll
        for (int c = 0; c < 4; c++) o[nt][c] = 0.f;

    float m0 = -1e30f, m1 = -1e30f, l0 = 0.f, l1 = 0.f;

    for (int j0 = 0; j0 < N_; j0 += 64) {
        __syncthreads();   // previous tile fully consumed
        // load + split K/V tile (64 keys x 64 dims)
        #pragma unroll
        for (int i = 0; i < 4; i++) {
            int lin = tid + i * 256;     // 0..1023
            int row = lin >> 4;          // 0..63
            int c4  = lin & 15;          // dim group (4 floats)
            float4 kv = *(const float4*)&Kbase[(size_t)(j0 + row) * 64 + c4 * 4];
            float4 vv = *(const float4*)&Vbase[(size_t)(j0 + row) * 64 + c4 * 4];
            __half kh0 = __float2half_rn(kv.x), kh1 = __float2half_rn(kv.y);
            __half kh2 = __float2half_rn(kv.z), kh3 = __float2half_rn(kv.w);
            __half vh0 = __float2half_rn(vv.x), vh1 = __float2half_rn(vv.y);
            __half vh2 = __float2half_rn(vv.z), vh3 = __float2half_rn(vv.w);
            uint2 pk;
            int off = row * KV_STRIDE + c4 * 4;
            pk.x = pkh(kh0, kh1); pk.y = pkh(kh2, kh3);
            *(uint2*)&Kh[off] = pk;
            pk.x = pkh(__float2half_rn(kv.x - __half2float(kh0)),
                       __float2half_rn(kv.y - __half2float(kh1)));
            pk.y = pkh(__float2half_rn(kv.z - __half2float(kh2)),
                       __float2half_rn(kv.w - __half2float(kh3)));
            *(uint2*)&Kl[off] = pk;
            pk.x = pkh(vh0, vh1); pk.y = pkh(vh2, vh3);
            *(uint2*)&Vh[off] = pk;
            pk.x = pkh(__float2half_rn(vv.x - __half2float(vh0)),
                       __float2half_rn(vv.y - __half2float(vh1)));
            pk.y = pkh(__float2half_rn(vv.z - __half2float(vh2)),
                       __float2half_rn(vv.w - __half2float(vh3)));
            *(uint2*)&Vl[off] = pk;
        }
        __syncthreads();

        // S = Q K^T : per nt (8-key tile), per kk (16-dim chunk): 3 fp16 MMAs
        float sc[8][4];
        #pragma unroll
        for (int nt = 0; nt < 8; nt++) {
            sc[nt][0] = sc[nt][1] = sc[nt][2] = sc[nt][3] = 0.f;
            const uint32_t aK = nt * (8 * KV_STRIDE * 2);
            #pragma unroll
            for (int kk = 0; kk < 4; kk++) {
                uint32_t bh0, bh1, bl0, bl1;
                LDSM_X2(bh0, bh1, smKh + aK + kOfs + kk * 32);
                LDSM_X2(bl0, bl1, smKl + aK + kOfs + kk * 32);
                mma_f16(sc[nt], qh[kk], bh0, bh1);
                mma_f16(sc[nt], qh[kk], bl0, bl1);
                mma_f16(sc[nt], ql[kk], bh0, bh1);
            }
        }

        // online softmax (rows g and g+8)
        float tm0 = -1e30f, tm1 = -1e30f;
        #pragma unroll
        for (int nt = 0; nt < 8; nt++) {
            tm0 = fmaxf(tm0, fmaxf(sc[nt][0], sc[nt][1]));
            tm1 = fmaxf(tm1, fmaxf(sc[nt][2], sc[nt][3]));
        }
        tm0 = fmaxf(tm0, __shfl_xor_sync(0xffffffffu, tm0, 1));
        tm0 = fmaxf(tm0, __shfl_xor_sync(0xffffffffu, tm0, 2));
        tm1 = fmaxf(tm1, __shfl_xor_sync(0xffffffffu, tm1, 1));
        tm1 = fmaxf(tm1, __shfl_xor_sync(0xffffffffu, tm1, 2));

        float m0n = fmaxf(m0, tm0);
        float m1n = fmaxf(m1, tm1);
        float cr0 = __expf(m0 - m0n);
        float cr1 = __expf(m1 - m1n);

        // exp + register-only P hi/lo packing
        uint32_t ph2[8][2], pl2[8][2];
        float rs0 = 0.f, rs1 = 0.f;
        #pragma unroll
        for (int nt = 0; nt < 8; nt++) {
            float p0 = __expf(sc[nt][0] - m0n);
            float p1 = __expf(sc[nt][1] - m0n);
            float p2 = __expf(sc[nt][2] - m1n);
            float p3 = __expf(sc[nt][3] - m1n);
            rs0 += p0 + p1;
            rs1 += p2 + p3;
            __half h0 = __float2half_rn(p0), h1 = __float2half_rn(p1);
            __half h2 = __float2half_rn(p2), h3 = __float2half_rn(p3);
            ph2[nt][0] = pkh(h0, h1);
            ph2[nt][1] = pkh(h2, h3);
            pl2[nt][0] = pkh(__float2half_rn(p0 - __half2float(h0)),
                             __float2half_rn(p1 - __half2float(h1)));
            pl2[nt][1] = pkh(__float2half_rn(p2 - __half2float(h2)),
                             __float2half_rn(p3 - __half2float(h3)));
        }
        rs0 += __shfl_xor_sync(0xffffffffu, rs0, 1);
        rs0 += __shfl_xor_sync(0xffffffffu, rs0, 2);
        rs1 += __shfl_xor_sync(0xffffffffu, rs1, 1);
        rs1 += __shfl_xor_sync(0xffffffffu, rs1, 2);

        l0 = l0 * cr0 + rs0;
        l1 = l1 * cr1 + rs1;
        m0 = m0n; m1 = m1n;
        #pragma unroll
        for (int nt = 0; nt < 8; nt++) {
            o[nt][0] *= cr0; o[nt][1] *= cr0;
            o[nt][2] *= cr1; o[nt][3] *= cr1;
        }

        // O += P V : per kk (16-key chunk): A from registers, B via ldmatrix.trans
        #pragma unroll
        for (int kk = 0; kk < 4; kk++) {
            uint32_t ah[4] = { ph2[2*kk][0], ph2[2*kk][1], ph2[2*kk+1][0], ph2[2*kk+1][1] };
            uint32_t al[4] = { pl2[2*kk][0], pl2[2*kk][1], pl2[2*kk+1][0], pl2[2*kk+1][1] };
            const uint32_t aV = kk * (16 * KV_STRIDE * 2);
            #pragma unroll
            for (int nt2 = 0; nt2 < 8; nt2++) {
                uint32_t bh0, bh1, bl0, bl1;
                LDSM_X2T(bh0, bh1, smVh + aV + vOfs + nt2 * 16);
                LDSM_X2T(bl0, bl1, smVl + aV + vOfs + nt2 * 16);
                mma_f16(o[nt2], ah, bh0, bh1);
                mma_f16(o[nt2], ah, bl0, bl1);
                mma_f16(o[nt2], al, bh0, bh1);
            }
        }
    }

    // write out: g_attn[b*N+q][h*64+d]
    const float inv0 = 1.f / l0;
    const float inv1 = 1.f / l1;
    float* d0 = g_attn + ((size_t)b * N_ + q0 + g    ) * C_ + (size_t)h * 64;
    float* d1 = g_attn + ((size_t)b * N_ + q0 + g + 8) * C_ + (size_t)h * 64;
    #pragma unroll
    for (int nt = 0; nt < 8; nt++) {
        int col = nt * 8 + 2 * tg;
        *(float2*)&d0[col] = make_float2(o[nt][0] * inv0, o[nt][1] * inv0);
        *(float2*)&d1[col] = make_float2(o[nt][2] * inv1, o[nt][3] * inv1);
    }
}

// ----------------------------------------------------------------------------
extern "C" void kernel_launch(void* const* d_in, const int* in_sizes, int n_in,
                              void* d_out, int out_size)
{
    const float* x      = (const float*)d_in[0];   // [B,N,C]
    const float* W_qkv  = (const float*)d_in[1];   // [3C,C]
    const float* W_proj = (const float*)d_in[2];   // [C,C]
    const float* b_proj = (const float*)d_in[3];   // [C]
    float* out = (float*)d_out;                    // [B,N,C]

    gemm_tf32<0><<<dim3(3*C_/128, M_/128), 256>>>(x, W_qkv, nullptr, nullptr,
                                                  M_, 3*C_, C_);
    flash_f16<<<dim3(N_/128, H_, B_), 256>>>();
    gemm_tf32<1><<<dim3(C_/128, M_/128), 256>>>(nullptr, W_proj, b_proj, out,
                                                M_, C_, C_);
}

// round 7
// speedup vs baseline: 3.5835x; 1.1434x over previous
#include <cuda_runtime.h>
#include <cuda_fp16.h>
#include <cstdint>

#define B_ 4
#define N_ 2048
#define C_ 1024
#define H_ 16
#define D_ 64
#define M_ (B_*N_)              // 8192 tokens
#define BHND (B_*H_*N_*D_)      // 8388608 elements per Q/K/V tensor

// Scratch (alloc-free rule: __device__ globals)
__device__ float g_qkv[(size_t)3*BHND];      // [s][b][h][n][d]
__device__ float g_attn[(size_t)M_*C_];      // [b*N+n][h*D+d]  (tf32-rounded)
// tf32-pre-rounded inputs
__device__ float g_xt [(size_t)M_*C_];
__device__ float g_wqt[(size_t)3*C_*C_];
__device__ float g_wpt[(size_t)C_*C_];

// ---------------------------------------------------------------- helpers ---
__device__ __forceinline__ uint32_t f2tf(float x) {
    uint32_t r; asm("cvt.rna.tf32.f32 %0, %1;" : "=r"(r) : "f"(x)); return r;
}

__device__ __forceinline__ void mma_tf32(float* c, const uint32_t* a,
                                         uint32_t b0, uint32_t b1) {
    asm volatile(
        "mma.sync.aligned.m16n8k8.row.col.f32.tf32.tf32.f32 "
        "{%0,%1,%2,%3}, {%4,%5,%6,%7}, {%8,%9}, {%0,%1,%2,%3};"
        : "+f"(c[0]), "+f"(c[1]), "+f"(c[2]), "+f"(c[3])
        : "r"(a[0]), "r"(a[1]), "r"(a[2]), "r"(a[3]), "r"(b0), "r"(b1));
}

__device__ __forceinline__ void mma_f16(float* c, const uint32_t* a,
                                        uint32_t b0, uint32_t b1) {
    asm volatile(
        "mma.sync.aligned.m16n8k16.row.col.f32.f16.f16.f32 "
        "{%0,%1,%2,%3}, {%4,%5,%6,%7}, {%8,%9}, {%0,%1,%2,%3};"
        : "+f"(c[0]), "+f"(c[1]), "+f"(c[2]), "+f"(c[3])
        : "r"(a[0]), "r"(a[1]), "r"(a[2]), "r"(a[3]), "r"(b0), "r"(b1));
}

__device__ __forceinline__ uint32_t smem_u32(const void* p) {
    uint32_t a;
    asm("{ .reg .u64 t; cvta.to.shared.u64 t, %1; cvt.u32.u64 %0, t; }"
        : "=r"(a) : "l"(p));
    return a;
}

#define LDSM_X2(r0, r1, addr) \
    asm volatile("ldmatrix.sync.aligned.m8n8.x2.shared.b16 {%0,%1}, [%2];" \
                 : "=r"(r0), "=r"(r1) : "r"(addr))
#define LDSM_X2T(r0, r1, addr) \
    asm volatile("ldmatrix.sync.aligned.m8n8.x2.trans.shared.b16 {%0,%1}, [%2];" \
                 : "=r"(r0), "=r"(r1) : "r"(addr))
#define LDSM_X4(r0, r1, r2, r3, addr) \
    asm volatile("ldmatrix.sync.aligned.m8n8.x4.shared.b16 {%0,%1,%2,%3}, [%4];" \
                 : "=r"(r0), "=r"(r1), "=r"(r2), "=r"(r3) : "r"(addr))

__device__ __forceinline__ void cp16(uint32_t dst, const void* src) {
    asm volatile("cp.async.cg.shared.global [%0], [%1], 16;" :: "r"(dst), "l"(src));
}
#define CP_COMMIT() asm volatile("cp.async.commit_group;" ::: "memory")
#define CP_WAIT(n)  asm volatile("cp.async.wait_group %0;" :: "n"(n) : "memory")

__device__ __forceinline__ uint32_t pkh(__half a, __half b) {
    __half2 h = __halves2half2(a, b);
    return *(uint32_t*)&h;
}

// ------------------------------------------------------ tf32 pre-rounding ---
// T=0: x -> g_xt ; T=1: W_qkv -> g_wqt ; T=2: W_proj -> g_wpt
template<int T>
__global__ void conv_tf32(const float* __restrict__ src, int n4) {
    int i = blockIdx.x * blockDim.x + threadIdx.x;
    if (i >= n4) return;
    float* dst = (T == 0) ? g_xt : (T == 1) ? g_wqt : g_wpt;
    float4 v = ((const float4*)src)[i];
    uint4 u = make_uint4(f2tf(v.x), f2tf(v.y), f2tf(v.z), f2tf(v.w));
    ((uint4*)dst)[i] = u;
}

// ----------------------------------------------------------------------------
// tf32 GEMM v2: C = A @ W^T (+bias). A [M,1024] rm, W [Nc,1024] rm, both
// tf32-pre-rounded. 128x128 CTA tile, 128 threads = 4 warps (2m x 2n),
// warp tile 64x64. 3-stage cp.async pipeline (k16 slabs).
// Smem rows padded to 20 floats (80B): 16B-aligned rows, conflict-free
// ldmatrix. Fragments loaded with ldmatrix.x4 (b16-on-tf32 trick).
// MODE 0: A=g_xt,  B=g_wqt, scatter -> g_qkv. MODE 1: A=g_attn, B=g_wpt, +bias.
// ----------------------------------------------------------------------------
#define ROWB 80                         // bytes per smem row (20 floats)
#define TILEB (128 * ROWB)              // 10240 B per A or B slab
#define GEMM2_SMEM (6 * TILEB)          // 3 stages x (A+B) = 61440 B

template<int MODE>
__global__ __launch_bounds__(128) void gemm_v2(const float* __restrict__ bias,
                                               float* __restrict__ out)
{
    extern __shared__ char smc[];
    const uint32_t sb = smem_u32(smc);

    const int tid  = threadIdx.x;
    const int warp = tid >> 5;
    const int lane = tid & 31;
    const int g    = lane >> 2;
    const int tg   = lane & 3;
    const int warpM = (warp >> 1) * 64;
    const int warpN = (warp & 1) * 64;
    const int m0 = blockIdx.y * 128;
    const int n0 = blockIdx.x * 128;

    const float* Ap = (MODE == 0) ? g_xt  : g_attn;
    const float* Bp = (MODE == 0) ? g_wqt : g_wpt;

    // per-lane ldmatrix byte offsets (within a stage slab)
    const uint32_t aLane = (uint32_t)((lane & 15) * ROWB + (lane >> 4) * 16);
    const uint32_t bLane = (uint32_t)(((lane & 7) + ((lane >> 4) & 1) * 8) * ROWB
                                      + ((lane >> 3) & 1) * 16);

    float acc[4][8][4];
    #pragma unroll
    for (int mt = 0; mt < 4; mt++)
        #pragma unroll
        for (int nt = 0; nt < 8; nt++)
            #pragma unroll
            for (int c = 0; c < 4; c++) acc[mt][nt][c] = 0.f;

    // cp.async one k16 slab (A 128x16 + B 128x16) into stage st
    auto loadStage = [&](int st, int k0) {
        const uint32_t aBase = sb + st * TILEB;
        const uint32_t bBase = sb + 3 * TILEB + st * TILEB;
        #pragma unroll
        for (int i = 0; i < 4; i++) {
            int chunk = tid + i * 128;          // 0..511
            int r = chunk >> 2;                 // 0..127
            int c = chunk & 3;                  // 0..3 (16B chunks)
            cp16(aBase + r * ROWB + c * 16, Ap + (size_t)(m0 + r) * 1024 + k0 + c * 4);
            cp16(bBase + r * ROWB + c * 16, Bp + (size_t)(n0 + r) * 1024 + k0 + c * 4);
        }
        CP_COMMIT();
    };

    loadStage(0, 0);
    loadStage(1, 16);

    for (int it = 0; it < 64; it++) {
        const int st = it % 3;
        if (it == 63) { CP_WAIT(0); } else { CP_WAIT(1); }
        __syncthreads();

        if (it + 2 < 64) loadStage((it + 2) % 3, (it + 2) * 16);

        const uint32_t aS = sb + st * TILEB + (uint32_t)warpM * ROWB;
        const uint32_t bS = sb + 3 * TILEB + st * TILEB + (uint32_t)warpN * ROWB;

        #pragma unroll
        for (int k8 = 0; k8 < 2; k8++) {
            uint32_t af[4][4], bf[4][4];
            #pragma unroll
            for (int mt = 0; mt < 4; mt++)
                LDSM_X4(af[mt][0], af[mt][1], af[mt][2], af[mt][3],
                        aS + mt * (16 * ROWB) + k8 * 32 + aLane);
            #pragma unroll
            for (int nt2 = 0; nt2 < 4; nt2++)
                LDSM_X4(bf[nt2][0], bf[nt2][1], bf[nt2][2], bf[nt2][3],
                        bS + nt2 * (16 * ROWB) + k8 * 32 + bLane);
            #pragma unroll
            for (int mt = 0; mt < 4; mt++)
                #pragma unroll
                for (int nt = 0; nt < 8; nt++)
                    mma_tf32(acc[mt][nt], af[mt],
                             bf[nt >> 1][(nt & 1) * 2], bf[nt >> 1][(nt & 1) * 2 + 1]);
        }
    }

    // epilogue
    #pragma unroll
    for (int mt = 0; mt < 4; mt++) {
        #pragma unroll
        for (int r = 0; r < 2; r++) {
            int m = m0 + warpM + mt * 16 + g + r * 8;
            #pragma unroll
            for (int nt = 0; nt < 8; nt++) {
                int col = n0 + warpN + nt * 8 + tg * 2;
                float2 v;
                v.x = acc[mt][nt][r * 2 + 0];
                v.y = acc[mt][nt][r * 2 + 1];
                if (MODE == 0) {
                    int s   = col >> 10;
                    int rem = col & 1023;
                    int h   = rem >> 6;
                    int d   = rem & 63;
                    int b   = m >> 11;
                    int ntk = m & (N_ - 1);
                    size_t dst = (size_t)s * BHND +
                                 ((((size_t)b * H_ + h) * N_ + ntk) * D_ + d);
                    *(float2*)&g_qkv[dst] = v;
                } else {
                    float2 bb = *(const float2*)&bias[col];
                    v.x += bb.x; v.y += bb.y;
                    *(float2*)&out[(size_t)m * 1024 + col] = v;
                }
            }
        }
    }
}

// ----------------------------------------------------------------------------
// fp16-split tensor-core flash attention (unchanged from R6 except epilogue
// applies tf32 rounding so gemm1 can consume g_attn without converting).
// ----------------------------------------------------------------------------
#define KV_STRIDE 72           // halves per row

__global__ __launch_bounds__(256, 1) void flash_f16()
{
    __shared__ __half Kh[64 * KV_STRIDE];
    __shared__ __half Kl[64 * KV_STRIDE];
    __shared__ __half Vh[64 * KV_STRIDE];
    __shared__ __half Vl[64 * KV_STRIDE];

    const int tid  = threadIdx.x;
    const int warp = tid >> 5;
    const int lane = tid & 31;
    const int g    = lane >> 2;
    const int tg   = lane & 3;

    const int b = blockIdx.z;
    const int h = blockIdx.y;
    const int q0 = blockIdx.x * 128 + warp * 16;

    const float* Qp    = g_qkv + (((size_t)b * H_ + h) * N_ + q0) * D_;
    const float* Kbase = g_qkv + (size_t)BHND     + (((size_t)b * H_ + h) * N_) * D_;
    const float* Vbase = g_qkv + (size_t)2 * BHND + (((size_t)b * H_ + h) * N_) * D_;

    const uint32_t smKh = smem_u32(Kh), smKl = smem_u32(Kl);
    const uint32_t smVh = smem_u32(Vh), smVl = smem_u32(Vl);
    const uint32_t kOfs = (uint32_t)(((lane & 7) * KV_STRIDE + ((lane >> 3) & 1) * 8) * 2);
    const uint32_t vOfs = (uint32_t)((lane & 15) * KV_STRIDE * 2);

    uint32_t qh[4][4], ql[4][4];
    #pragma unroll
    for (int kk = 0; kk < 4; kk++) {
        const int d0 = kk * 16 + 2 * tg;
        #pragma unroll
        for (int half8 = 0; half8 < 2; half8++) {
            #pragma unroll
            for (int r = 0; r < 2; r++) {
                float v0 = Qp[(size_t)(g + r * 8) * 64 + d0 + half8 * 8    ] * 0.125f;
                float v1 = Qp[(size_t)(g + r * 8) * 64 + d0 + half8 * 8 + 1] * 0.125f;
                __half h0 = __float2half_rn(v0), h1 = __float2half_rn(v1);
                __half l0 = __float2half_rn(v0 - __half2float(h0));
                __half l1 = __float2half_rn(v1 - __half2float(h1));
                qh[kk][half8 * 2 + r] = pkh(h0, h1);
                ql[kk][half8 * 2 + r] = pkh(l0, l1);
            }
        }
    }

    float o[8][4];
    #pragma unroll
    for (int nt = 0; nt < 8; nt++)
        #pragma unroll
        for (int c = 0; c < 4; c++) o[nt][c] = 0.f;

    float m0 = -1e30f, m1 = -1e30f, l0 = 0.f, l1 = 0.f;

    for (int j0 = 0; j0 < N_; j0 += 64) {
        __syncthreads();
        #pragma unroll
        for (int i = 0; i < 4; i++) {
            int lin = tid + i * 256;
            int row = lin >> 4;
            int c4  = lin & 15;
            float4 kv = *(const float4*)&Kbase[(size_t)(j0 + row) * 64 + c4 * 4];
            float4 vv = *(const float4*)&Vbase[(size_t)(j0 + row) * 64 + c4 * 4];
            __half kh0 = __float2half_rn(kv.x), kh1 = __float2half_rn(kv.y);
            __half kh2 = __float2half_rn(kv.z), kh3 = __float2half_rn(kv.w);
            __half vh0 = __float2half_rn(vv.x), vh1 = __float2half_rn(vv.y);
            __half vh2 = __float2half_rn(vv.z), vh3 = __float2half_rn(vv.w);
            uint2 pk;
            int off = row * KV_STRIDE + c4 * 4;
            pk.x = pkh(kh0, kh1); pk.y = pkh(kh2, kh3);
            *(uint2*)&Kh[off] = pk;
            pk.x = pkh(__float2half_rn(kv.x - __half2float(kh0)),
                       __float2half_rn(kv.y - __half2float(kh1)));
            pk.y = pkh(__float2half_rn(kv.z - __half2float(kh2)),
                       __float2half_rn(kv.w - __half2float(kh3)));
            *(uint2*)&Kl[off] = pk;
            pk.x = pkh(vh0, vh1); pk.y = pkh(vh2, vh3);
            *(uint2*)&Vh[off] = pk;
            pk.x = pkh(__float2half_rn(vv.x - __half2float(vh0)),
                       __float2half_rn(vv.y - __half2float(vh1)));
            pk.y = pkh(__float2half_rn(vv.z - __half2float(vh2)),
                       __float2half_rn(vv.w - __half2float(vh3)));
            *(uint2*)&Vl[off] = pk;
        }
        __syncthreads();

        float sc[8][4];
        #pragma unroll
        for (int nt = 0; nt < 8; nt++) {
            sc[nt][0] = sc[nt][1] = sc[nt][2] = sc[nt][3] = 0.f;
            const uint32_t aK = nt * (8 * KV_STRIDE * 2);
            #pragma unroll
            for (int kk = 0; kk < 4; kk++) {
                uint32_t bh0, bh1, bl0, bl1;
                LDSM_X2(bh0, bh1, smKh + aK + kOfs + kk * 32);
                LDSM_X2(bl0, bl1, smKl + aK + kOfs + kk * 32);
                mma_f16(sc[nt], qh[kk], bh0, bh1);
                mma_f16(sc[nt], qh[kk], bl0, bl1);
                mma_f16(sc[nt], ql[kk], bh0, bh1);
            }
        }

        float tm0 = -1e30f, tm1 = -1e30f;
        #pragma unroll
        for (int nt = 0; nt < 8; nt++) {
            tm0 = fmaxf(tm0, fmaxf(sc[nt][0], sc[nt][1]));
            tm1 = fmaxf(tm1, fmaxf(sc[nt][2], sc[nt][3]));
        }
        tm0 = fmaxf(tm0, __shfl_xor_sync(0xffffffffu, tm0, 1));
        tm0 = fmaxf(tm0, __shfl_xor_sync(0xffffffffu, tm0, 2));
        tm1 = fmaxf(tm1, __shfl_xor_sync(0xffffffffu, tm1, 1));
        tm1 = fmaxf(tm1, __shfl_xor_sync(0xffffffffu, tm1, 2));

        float m0n = fmaxf(m0, tm0);
        float m1n = fmaxf(m1, tm1);
        float cr0 = __expf(m0 - m0n);
        float cr1 = __expf(m1 - m1n);

        uint32_t ph2[8][2], pl2[8][2];
        float rs0 = 0.f, rs1 = 0.f;
        #pragma unroll
        for (int nt = 0; nt < 8; nt++) {
            float p0 = __expf(sc[nt][0] - m0n);
            float p1 = __expf(sc[nt][1] - m0n);
            float p2 = __expf(sc[nt][2] - m1n);
            float p3 = __expf(sc[nt][3] - m1n);
            rs0 += p0 + p1;
            rs1 += p2 + p3;
            __half h0 = __float2half_rn(p0), h1 = __float2half_rn(p1);
            __half h2 = __float2half_rn(p2), h3 = __float2half_rn(p3);
            ph2[nt][0] = pkh(h0, h1);
            ph2[nt][1] = pkh(h2, h3);
            pl2[nt][0] = pkh(__float2half_rn(p0 - __half2float(h0)),
                             __float2half_rn(p1 - __half2float(h1)));
            pl2[nt][1] = pkh(__float2half_rn(p2 - __half2float(h2)),
                             __float2half_rn(p3 - __half2float(h3)));
        }
        rs0 += __shfl_xor_sync(0xffffffffu, rs0, 1);
        rs0 += __shfl_xor_sync(0xffffffffu, rs0, 2);
        rs1 += __shfl_xor_sync(0xffffffffu, rs1, 1);
        rs1 += __shfl_xor_sync(0xffffffffu, rs1, 2);

        l0 = l0 * cr0 + rs0;
        l1 = l1 * cr1 + rs1;
        m0 = m0n; m1 = m1n;
        #pragma unroll
        for (int nt = 0; nt < 8; nt++) {
            o[nt][0] *= cr0; o[nt][1] *= cr0;
            o[nt][2] *= cr1; o[nt][3] *= cr1;
        }

        #pragma unroll
        for (int kk = 0; kk < 4; kk++) {
            uint32_t ah[4] = { ph2[2*kk][0], ph2[2*kk][1], ph2[2*kk+1][0], ph2[2*kk+1][1] };
            uint32_t al[4] = { pl2[2*kk][0], pl2[2*kk][1], pl2[2*kk+1][0], pl2[2*kk+1][1] };
            const uint32_t aV = kk * (16 * KV_STRIDE * 2);
            #pragma unroll
            for (int nt2 = 0; nt2 < 8; nt2++) {
                uint32_t bh0, bh1, bl0, bl1;
                LDSM_X2T(bh0, bh1, smVh + aV + vOfs + nt2 * 16);
                LDSM_X2T(bl0, bl1, smVl + aV + vOfs + nt2 * 16);
                mma_f16(o[nt2], ah, bh0, bh1);
                mma_f16(o[nt2], ah, bl0, bl1);
                mma_f16(o[nt2], al, bh0, bh1);
            }
        }
    }

    // write out (tf32-rounded so gemm1 reads it raw)
    const float inv0 = 1.f / l0;
    const float inv1 = 1.f / l1;
    float* d0 = g_attn + ((size_t)b * N_ + q0 + g    ) * C_ + (size_t)h * 64;
    float* d1 = g_attn + ((size_t)b * N_ + q0 + g + 8) * C_ + (size_t)h * 64;
    #pragma unroll
    for (int nt = 0; nt < 8; nt++) {
        int col = nt * 8 + 2 * tg;
        uint2 w0 = make_uint2(f2tf(o[nt][0] * inv0), f2tf(o[nt][1] * inv0));
        uint2 w1 = make_uint2(f2tf(o[nt][2] * inv1), f2tf(o[nt][3] * inv1));
        *(uint2*)&d0[col] = w0;
        *(uint2*)&d1[col] = w1;
    }
}

// ----------------------------------------------------------------------------
extern "C" void kernel_launch(void* const* d_in, const int* in_sizes, int n_in,
                              void* d_out, int out_size)
{
    const float* x      = (const float*)d_in[0];   // [B,N,C]
    const float* W_qkv  = (const float*)d_in[1];   // [3C,C]
    const float* W_proj = (const float*)d_in[2];   // [C,C]
    const float* b_proj = (const float*)d_in[3];   // [C]
    float* out = (float*)d_out;                    // [B,N,C]

    cudaFuncSetAttribute(gemm_v2<0>, cudaFuncAttributeMaxDynamicSharedMemorySize,
                         GEMM2_SMEM);
    cudaFuncSetAttribute(gemm_v2<1>, cudaFuncAttributeMaxDynamicSharedMemorySize,
                         GEMM2_SMEM);

    // tf32 pre-rounding of GEMM operands
    conv_tf32<0><<<(M_*C_/4 + 255)/256, 256>>>(x,      M_*C_/4);
    conv_tf32<1><<<(3*C_*C_/4 + 255)/256, 256>>>(W_qkv, 3*C_*C_/4);
    conv_tf32<2><<<(C_*C_/4 + 255)/256, 256>>>(W_proj, C_*C_/4);

    // QKV projection -> g_qkv
    gemm_v2<0><<<dim3(3*C_/128, M_/128), 128, GEMM2_SMEM>>>(nullptr, nullptr);
    // flash attention -> g_attn (tf32-rounded)
    flash_f16<<<dim3(N_/128, H_, B_), 256>>>();
    // output projection + bias -> d_out
    gemm_v2<1><<<dim3(C_/128, M_/128), 128, GEMM2_SMEM>>>(b_proj, out);
}

// round 8
// speedup vs baseline: 3.9253x; 1.0954x over previous
#include <cuda_runtime.h>
#include <cuda_fp16.h>
#include <cstdint>

#define B_ 4
#define N_ 2048
#define C_ 1024
#define H_ 16
#define D_ 64
#define M_ (B_*N_)              // 8192 tokens
#define BHND (B_*H_*N_*D_)      // 8388608 elements per head-split tensor

// Scratch (alloc-free rule: __device__ globals)
__device__ float g_qkv[(size_t)BHND];        // Q only, fp32 [b][h][n][d]
__device__ float g_attn[(size_t)M_*C_];      // [b*N+n][h*D+d]  (tf32-rounded)
// K/V pre-split fp16 (written by gemm0 epilogue)
__device__ __align__(16) __half g_kh[(size_t)BHND];
__device__ __align__(16) __half g_kl[(size_t)BHND];
__device__ __align__(16) __half g_vh[(size_t)BHND];
__device__ __align__(16) __half g_vl[(size_t)BHND];
// tf32-pre-rounded inputs
__device__ float g_xt [(size_t)M_*C_];
__device__ float g_wqt[(size_t)3*C_*C_];
__device__ float g_wpt[(size_t)C_*C_];

// ---------------------------------------------------------------- helpers ---
__device__ __forceinline__ uint32_t f2tf(float x) {
    uint32_t r; asm("cvt.rna.tf32.f32 %0, %1;" : "=r"(r) : "f"(x)); return r;
}

__device__ __forceinline__ void mma_tf32(float* c, const uint32_t* a,
                                         uint32_t b0, uint32_t b1) {
    asm volatile(
        "mma.sync.aligned.m16n8k8.row.col.f32.tf32.tf32.f32 "
        "{%0,%1,%2,%3}, {%4,%5,%6,%7}, {%8,%9}, {%0,%1,%2,%3};"
        : "+f"(c[0]), "+f"(c[1]), "+f"(c[2]), "+f"(c[3])
        : "r"(a[0]), "r"(a[1]), "r"(a[2]), "r"(a[3]), "r"(b0), "r"(b1));
}

__device__ __forceinline__ void mma_f16(float* c, const uint32_t* a,
                                        uint32_t b0, uint32_t b1) {
    asm volatile(
        "mma.sync.aligned.m16n8k16.row.col.f32.f16.f16.f32 "
        "{%0,%1,%2,%3}, {%4,%5,%6,%7}, {%8,%9}, {%0,%1,%2,%3};"
        : "+f"(c[0]), "+f"(c[1]), "+f"(c[2]), "+f"(c[3])
        : "r"(a[0]), "r"(a[1]), "r"(a[2]), "r"(a[3]), "r"(b0), "r"(b1));
}

__device__ __forceinline__ uint32_t smem_u32(const void* p) {
    uint32_t a;
    asm("{ .reg .u64 t; cvta.to.shared.u64 t, %1; cvt.u32.u64 %0, t; }"
        : "=r"(a) : "l"(p));
    return a;
}

#define LDSM_X2(r0, r1, addr) \
    asm volatile("ldmatrix.sync.aligned.m8n8.x2.shared.b16 {%0,%1}, [%2];" \
                 : "=r"(r0), "=r"(r1) : "r"(addr))
#define LDSM_X2T(r0, r1, addr) \
    asm volatile("ldmatrix.sync.aligned.m8n8.x2.trans.shared.b16 {%0,%1}, [%2];" \
                 : "=r"(r0), "=r"(r1) : "r"(addr))
#define LDSM_X4(r0, r1, r2, r3, addr) \
    asm volatile("ldmatrix.sync.aligned.m8n8.x4.shared.b16 {%0,%1,%2,%3}, [%4];" \
                 : "=r"(r0), "=r"(r1), "=r"(r2), "=r"(r3) : "r"(addr))

__device__ __forceinline__ void cp16(uint32_t dst, const void* src) {
    asm volatile("cp.async.cg.shared.global [%0], [%1], 16;" :: "r"(dst), "l"(src));
}
#define CP_COMMIT() asm volatile("cp.async.commit_group;" ::: "memory")
#define CP_WAIT(n)  asm volatile("cp.async.wait_group %0;" :: "n"(n) : "memory")

__device__ __forceinline__ uint32_t pkh(__half a, __half b) {
    __half2 h = __halves2half2(a, b);
    return *(uint32_t*)&h;
}

// ------------------------------------------------------ tf32 pre-rounding ---
template<int T>
__global__ void conv_tf32(const float* __restrict__ src, int n4) {
    int i = blockIdx.x * blockDim.x + threadIdx.x;
    if (i >= n4) return;
    float* dst = (T == 0) ? g_xt : (T == 1) ? g_wqt : g_wpt;
    float4 v = ((const float4*)src)[i];
    uint4 u = make_uint4(f2tf(v.x), f2tf(v.y), f2tf(v.z), f2tf(v.w));
    ((uint4*)dst)[i] = u;
}

// ----------------------------------------------------------------------------
// tf32 GEMM v2 (as R7): 128x128 CTA, 4 warps, 64x64 warp tiles, 3-stage
// cp.async, ldmatrix-b16 fragment loads.
// MODE 0 epilogue: Q -> g_qkv (fp32); K,V -> g_kh/g_kl, g_vh/g_vl (fp16 split).
// MODE 1 epilogue: + bias -> out.
// ----------------------------------------------------------------------------
#define ROWB 80
#define TILEB (128 * ROWB)
#define GEMM2_SMEM (6 * TILEB)

template<int MODE>
__global__ __launch_bounds__(128) void gemm_v2(const float* __restrict__ bias,
                                               float* __restrict__ out)
{
    extern __shared__ char smc[];
    const uint32_t sb = smem_u32(smc);

    const int tid  = threadIdx.x;
    const int warp = tid >> 5;
    const int lane = tid & 31;
    const int g    = lane >> 2;
    const int tg   = lane & 3;
    const int warpM = (warp >> 1) * 64;
    const int warpN = (warp & 1) * 64;
    const int m0 = blockIdx.y * 128;
    const int n0 = blockIdx.x * 128;

    const float* Ap = (MODE == 0) ? g_xt  : g_attn;
    const float* Bp = (MODE == 0) ? g_wqt : g_wpt;

    const uint32_t aLane = (uint32_t)((lane & 15) * ROWB + (lane >> 4) * 16);
    const uint32_t bLane = (uint32_t)(((lane & 7) + ((lane >> 4) & 1) * 8) * ROWB
                                      + ((lane >> 3) & 1) * 16);

    float acc[4][8][4];
    #pragma unroll
    for (int mt = 0; mt < 4; mt++)
        #pragma unroll
        for (int nt = 0; nt < 8; nt++)
            #pragma unroll
            for (int c = 0; c < 4; c++) acc[mt][nt][c] = 0.f;

    auto loadStage = [&](int st, int k0) {
        const uint32_t aBase = sb + st * TILEB;
        const uint32_t bBase = sb + 3 * TILEB + st * TILEB;
        #pragma unroll
        for (int i = 0; i < 4; i++) {
            int chunk = tid + i * 128;
            int r = chunk >> 2;
            int c = chunk & 3;
            cp16(aBase + r * ROWB + c * 16, Ap + (size_t)(m0 + r) * 1024 + k0 + c * 4);
            cp16(bBase + r * ROWB + c * 16, Bp + (size_t)(n0 + r) * 1024 + k0 + c * 4);
        }
        CP_COMMIT();
    };

    loadStage(0, 0);
    loadStage(1, 16);

    for (int it = 0; it < 64; it++) {
        const int st = it % 3;
        if (it == 63) { CP_WAIT(0); } else { CP_WAIT(1); }
        __syncthreads();

        if (it + 2 < 64) loadStage((it + 2) % 3, (it + 2) * 16);

        const uint32_t aS = sb + st * TILEB + (uint32_t)warpM * ROWB;
        const uint32_t bS = sb + 3 * TILEB + st * TILEB + (uint32_t)warpN * ROWB;

        #pragma unroll
        for (int k8 = 0; k8 < 2; k8++) {
            uint32_t af[4][4], bf[4][4];
            #pragma unroll
            for (int mt = 0; mt < 4; mt++)
                LDSM_X4(af[mt][0], af[mt][1], af[mt][2], af[mt][3],
                        aS + mt * (16 * ROWB) + k8 * 32 + aLane);
            #pragma unroll
            for (int nt2 = 0; nt2 < 4; nt2++)
                LDSM_X4(bf[nt2][0], bf[nt2][1], bf[nt2][2], bf[nt2][3],
                        bS + nt2 * (16 * ROWB) + k8 * 32 + bLane);
            #pragma unroll
            for (int mt = 0; mt < 4; mt++)
                #pragma unroll
                for (int nt = 0; nt < 8; nt++)
                    mma_tf32(acc[mt][nt], af[mt],
                             bf[nt >> 1][(nt & 1) * 2], bf[nt >> 1][(nt & 1) * 2 + 1]);
        }
    }

    // epilogue
    #pragma unroll
    for (int mt = 0; mt < 4; mt++) {
        #pragma unroll
        for (int r = 0; r < 2; r++) {
            int m = m0 + warpM + mt * 16 + g + r * 8;
            #pragma unroll
            for (int nt = 0; nt < 8; nt++) {
                int col = n0 + warpN + nt * 8 + tg * 2;
                float2 v;
                v.x = acc[mt][nt][r * 2 + 0];
                v.y = acc[mt][nt][r * 2 + 1];
                if (MODE == 0) {
                    int s   = col >> 10;
                    int rem = col & 1023;
                    int hh  = rem >> 6;
                    int d   = rem & 63;
                    int bb  = m >> 11;
                    int ntk = m & (N_ - 1);
                    size_t idx = (((size_t)bb * H_ + hh) * N_ + ntk) * D_ + d;
                    if (s == 0) {
                        *(float2*)&g_qkv[idx] = v;
                    } else {
                        __half h0 = __float2half_rn(v.x), h1 = __float2half_rn(v.y);
                        __half l0 = __float2half_rn(v.x - __half2float(h0));
                        __half l1 = __float2half_rn(v.y - __half2float(h1));
                        __half2 hv = __halves2half2(h0, h1);
                        __half2 lv = __halves2half2(l0, l1);
                        if (s == 1) {
                            *(__half2*)&g_kh[idx] = hv;
                            *(__half2*)&g_kl[idx] = lv;
                        } else {
                            *(__half2*)&g_vh[idx] = hv;
                            *(__half2*)&g_vl[idx] = lv;
                        }
                    }
                } else {
                    float2 bb = *(const float2*)&bias[col];
                    v.x += bb.x; v.y += bb.y;
                    *(float2*)&out[(size_t)m * 1024 + col] = v;
                }
            }
        }
    }
}

// ----------------------------------------------------------------------------
// fp16-split flash attention v2: K/V pre-split in gmem (fp16 hi/lo),
// 2-stage cp.async pipeline, no in-loop conversion.
// Block: 256 threads = 8 warps x 16 query rows; one (b,h) per block.
// ----------------------------------------------------------------------------
#define KV_STRIDE 72                           // halves per row (144 B)
#define FL_TILEB (64 * KV_STRIDE * 2)          // 9216 B per array
#define FLASH_SMEM (2 * 4 * FL_TILEB)          // 73728 B

__global__ __launch_bounds__(256, 1) void flash_f16()
{
    extern __shared__ char smc[];
    const uint32_t sb = smem_u32(smc);

    const int tid  = threadIdx.x;
    const int warp = tid >> 5;
    const int lane = tid & 31;
    const int g    = lane >> 2;
    const int tg   = lane & 3;

    const int b = blockIdx.z;
    const int h = blockIdx.y;
    const int q0 = blockIdx.x * 128 + warp * 16;

    const size_t kvoff = ((size_t)b * H_ + h) * N_ * D_;
    const float*  Qp = g_qkv + kvoff + (size_t)(q0 & (N_ - 1)) * 0 + ((size_t)q0 - ((size_t)b * 0)) * 0
                       + (((size_t)b * H_ + h) * N_ + q0) * 0;  // (computed below properly)
    const float*  Qbase = g_qkv + (((size_t)b * H_ + h) * N_ + q0) * D_;
    const __half* bases[4] = { g_kh + kvoff, g_kl + kvoff, g_vh + kvoff, g_vl + kvoff };

    const uint32_t kOfs = (uint32_t)(((lane & 7) * KV_STRIDE + ((lane >> 3) & 1) * 8) * 2);
    const uint32_t vOfs = (uint32_t)((lane & 15) * KV_STRIDE * 2);

    // Q fragments (scaled 0.125), fp16 hi/lo split
    uint32_t qh[4][4], ql[4][4];
    #pragma unroll
    for (int kk = 0; kk < 4; kk++) {
        const int d0 = kk * 16 + 2 * tg;
        #pragma unroll
        for (int half8 = 0; half8 < 2; half8++) {
            #pragma unroll
            for (int r = 0; r < 2; r++) {
                float v0 = Qbase[(size_t)(g + r * 8) * 64 + d0 + half8 * 8    ] * 0.125f;
                float v1 = Qbase[(size_t)(g + r * 8) * 64 + d0 + half8 * 8 + 1] * 0.125f;
                __half h0 = __float2half_rn(v0), h1 = __float2half_rn(v1);
                __half l0 = __float2half_rn(v0 - __half2float(h0));
                __half l1 = __float2half_rn(v1 - __half2float(h1));
                qh[kk][half8 * 2 + r] = pkh(h0, h1);
                ql[kk][half8 * 2 + r] = pkh(l0, l1);
            }
        }
    }

    // cp.async one K/V tile (4 arrays x 64 rows x 128B) into stage st
    auto loadTile = [&](int st, int j0) {
        const uint32_t base = sb + st * 4 * FL_TILEB;
        #pragma unroll
        for (int i = 0; i < 8; i++) {
            int lin = tid + i * 256;         // 0..2047
            int arr = lin >> 9;              // 0..3
            int r   = (lin >> 3) & 63;       // 0..63
            int c   = lin & 7;               // 0..7 (16B chunks)
            cp16(base + arr * FL_TILEB + r * (KV_STRIDE * 2) + c * 16,
                 bases[arr] + (size_t)(j0 + r) * 64 + c * 8);
        }
        CP_COMMIT();
    };

    float o[8][4];
    #pragma unroll
    for (int nt = 0; nt < 8; nt++)
        #pragma unroll
        for (int c = 0; c < 4; c++) o[nt][c] = 0.f;

    float m0 = -1e30f, m1 = -1e30f, l0 = 0.f, l1 = 0.f;

    loadTile(0, 0);

    for (int t = 0; t < 32; t++) {
        const int st = t & 1;
        if (t + 1 < 32) loadTile(st ^ 1, (t + 1) * 64);
        if (t + 1 < 32) { CP_WAIT(1); } else { CP_WAIT(0); }
        __syncthreads();

        const uint32_t smKh = sb + st * 4 * FL_TILEB;
        const uint32_t smKl = smKh + FL_TILEB;
        const uint32_t smVh = smKh + 2 * FL_TILEB;
        const uint32_t smVl = smKh + 3 * FL_TILEB;

        // S = Q K^T
        float sc[8][4];
        #pragma unroll
        for (int nt = 0; nt < 8; nt++) {
            sc[nt][0] = sc[nt][1] = sc[nt][2] = sc[nt][3] = 0.f;
            const uint32_t aK = nt * (8 * KV_STRIDE * 2);
            #pragma unroll
            for (int kk = 0; kk < 4; kk++) {
                uint32_t bh0, bh1, bl0, bl1;
                LDSM_X2(bh0, bh1, smKh + aK + kOfs + kk * 32);
                LDSM_X2(bl0, bl1, smKl + aK + kOfs + kk * 32);
                mma_f16(sc[nt], qh[kk], bh0, bh1);
                mma_f16(sc[nt], qh[kk], bl0, bl1);
                mma_f16(sc[nt], ql[kk], bh0, bh1);
            }
        }

        // online softmax
        float tm0 = -1e30f, tm1 = -1e30f;
        #pragma unroll
        for (int nt = 0; nt < 8; nt++) {
            tm0 = fmaxf(tm0, fmaxf(sc[nt][0], sc[nt][1]));
            tm1 = fmaxf(tm1, fmaxf(sc[nt][2], sc[nt][3]));
        }
        tm0 = fmaxf(tm0, __shfl_xor_sync(0xffffffffu, tm0, 1));
        tm0 = fmaxf(tm0, __shfl_xor_sync(0xffffffffu, tm0, 2));
        tm1 = fmaxf(tm1, __shfl_xor_sync(0xffffffffu, tm1, 1));
        tm1 = fmaxf(tm1, __shfl_xor_sync(0xffffffffu, tm1, 2));

        float m0n = fmaxf(m0, tm0);
        float m1n = fmaxf(m1, tm1);
        float cr0 = __expf(m0 - m0n);
        float cr1 = __expf(m1 - m1n);

        uint32_t ph2[8][2], pl2[8][2];
        float rs0 = 0.f, rs1 = 0.f;
        #pragma unroll
        for (int nt = 0; nt < 8; nt++) {
            float p0 = __expf(sc[nt][0] - m0n);
            float p1 = __expf(sc[nt][1] - m0n);
            float p2 = __expf(sc[nt][2] - m1n);
            float p3 = __expf(sc[nt][3] - m1n);
            rs0 += p0 + p1;
            rs1 += p2 + p3;
            __half h0 = __float2half_rn(p0), h1 = __float2half_rn(p1);
            __half h2 = __float2half_rn(p2), h3 = __float2half_rn(p3);
            ph2[nt][0] = pkh(h0, h1);
            ph2[nt][1] = pkh(h2, h3);
            pl2[nt][0] = pkh(__float2half_rn(p0 - __half2float(h0)),
                             __float2half_rn(p1 - __half2float(h1)));
            pl2[nt][1] = pkh(__float2half_rn(p2 - __half2float(h2)),
                             __float2half_rn(p3 - __half2float(h3)));
        }
        rs0 += __shfl_xor_sync(0xffffffffu, rs0, 1);
        rs0 += __shfl_xor_sync(0xffffffffu, rs0, 2);
        rs1 += __shfl_xor_sync(0xffffffffu, rs1, 1);
        rs1 += __shfl_xor_sync(0xffffffffu, rs1, 2);

        l0 = l0 * cr0 + rs0;
        l1 = l1 * cr1 + rs1;
        m0 = m0n; m1 = m1n;
        #pragma unroll
        for (int nt = 0; nt < 8; nt++) {
            o[nt][0] *= cr0; o[nt][1] *= cr0;
            o[nt][2] *= cr1; o[nt][3] *= cr1;
        }

        // O += P V
        #pragma unroll
        for (int kk = 0; kk < 4; kk++) {
            uint32_t ah[4] = { ph2[2*kk][0], ph2[2*kk][1], ph2[2*kk+1][0], ph2[2*kk+1][1] };
            uint32_t al[4] = { pl2[2*kk][0], pl2[2*kk][1], pl2[2*kk+1][0], pl2[2*kk+1][1] };
            const uint32_t aV = kk * (16 * KV_STRIDE * 2);
            #pragma unroll
            for (int nt2 = 0; nt2 < 8; nt2++) {
                uint32_t bh0, bh1, bl0, bl1;
                LDSM_X2T(bh0, bh1, smVh + aV + vOfs + nt2 * 16);
                LDSM_X2T(bl0, bl1, smVl + aV + vOfs + nt2 * 16);
                mma_f16(o[nt2], ah, bh0, bh1);
                mma_f16(o[nt2], ah, bl0, bl1);
                mma_f16(o[nt2], al, bh0, bh1);
            }
        }
        __syncthreads();   // stage st consumed; next iter may overwrite it
    }

    // write out (tf32-rounded for gemm1)
    const float inv0 = 1.f / l0;
    const float inv1 = 1.f / l1;
    float* d0 = g_attn + ((size_t)b * N_ + q0 + g    ) * C_ + (size_t)h * 64;
    float* d1 = g_attn + ((size_t)b * N_ + q0 + g + 8) * C_ + (size_t)h * 64;
    #pragma unroll
    for (int nt = 0; nt < 8; nt++) {
        int col = nt * 8 + 2 * tg;
        uint2 w0 = make_uint2(f2tf(o[nt][0] * inv0), f2tf(o[nt][1] * inv0));
        uint2 w1 = make_uint2(f2tf(o[nt][2] * inv1), f2tf(o[nt][3] * inv1));
        *(uint2*)&d0[col] = w0;
        *(uint2*)&d1[col] = w1;
    }
}

// ----------------------------------------------------------------------------
extern "C" void kernel_launch(void* const* d_in, const int* in_sizes, int n_in,
                              void* d_out, int out_size)
{
    const float* x      = (const float*)d_in[0];   // [B,N,C]
    const float* W_qkv  = (const float*)d_in[1];   // [3C,C]
    const float* W_proj = (const float*)d_in[2];   // [C,C]
    const float* b_proj = (const float*)d_in[3];   // [C]
    float* out = (float*)d_out;                    // [B,N,C]

    cudaFuncSetAttribute(gemm_v2<0>, cudaFuncAttributeMaxDynamicSharedMemorySize,
                         GEMM2_SMEM);
    cudaFuncSetAttribute(gemm_v2<1>, cudaFuncAttributeMaxDynamicSharedMemorySize,
                         GEMM2_SMEM);
    cudaFuncSetAttribute(flash_f16, cudaFuncAttributeMaxDynamicSharedMemorySize,
                         FLASH_SMEM);

    // tf32 pre-rounding of GEMM operands
    conv_tf32<0><<<(M_*C_/4 + 255)/256, 256>>>(x,      M_*C_/4);
    conv_tf32<1><<<(3*C_*C_/4 + 255)/256, 256>>>(W_qkv, 3*C_*C_/4);
    conv_tf32<2><<<(C_*C_/4 + 255)/256, 256>>>(W_proj, C_*C_/4);

    // QKV projection -> Q fp32, K/V fp16-split
    gemm_v2<0><<<dim3(3*C_/128, M_/128), 128, GEMM2_SMEM>>>(nullptr, nullptr);
    // flash attention -> g_attn (tf32-rounded)
    flash_f16<<<dim3(N_/128, H_, B_), 256, FLASH_SMEM>>>();
    // output projection + bias -> d_out
    gemm_v2<1><<<dim3(C_/128, M_/128), 128, GEMM2_SMEM>>>(b_proj, out);
}